// round 1
// baseline (speedup 1.0000x reference)
#include <cuda_runtime.h>
#include <math.h>

#define DM   512
#define NH   8
#define DH   64
#define BAT  2
#define SEQ  2048
#define NTOK (BAT*SEQ)   // 4096

// Scratch (device globals; no allocations allowed)
__device__ float g_q[BAT*NH*SEQ*DH];     // [B,H,S,d], pre-scaled by 1/sqrt(d)
__device__ float g_k[BAT*NH*SEQ*DH];
__device__ float g_v[BAT*NH*SEQ*DH];
__device__ float g_att[NTOK*DM];         // attention output in [B,S,D]

// ---------------------------------------------------------------------------
// GEMM: C[M=4096, N=512] = A[M,512] @ W[512,512]^T, epilogue (acc+bias)*scale
// SPLIT=true  -> write to [B,H,S,d] layout (split heads)
// SPLIT=false -> write to [B,S,D] (row-major [M,512])
// 64x64 block tile, 256 threads, 4x4 per thread (strided r/c mapping).
// ---------------------------------------------------------------------------
template<bool SPLIT>
__global__ __launch_bounds__(256)
void proj_kernel(const float* __restrict__ A, const float* __restrict__ W,
                 const float* __restrict__ bias, float* __restrict__ out,
                 float scale)
{
    __shared__ float As[64][17];
    __shared__ float Ws[64][17];

    const int tid  = threadIdx.x;
    const int tr   = tid >> 4;        // 0..15
    const int tc   = tid & 15;        // 0..15
    const int bn   = blockIdx.x;      // 0..7   (N blocks)
    const int bm   = blockIdx.y;      // 0..63  (M blocks)

    const int lr   = tid >> 2;        // load row 0..63
    const int lc   = (tid & 3) * 4;   // load col segment

    const float* Ag = A + (size_t)(bm*64 + lr)*DM;
    const float* Wg = W + (size_t)(bn*64 + lr)*DM;

    float acc[4][4];
#pragma unroll
    for (int i = 0; i < 4; i++)
#pragma unroll
        for (int j = 0; j < 4; j++) acc[i][j] = 0.f;

    for (int k0 = 0; k0 < DM; k0 += 16) {
        float4 a4 = *(const float4*)(Ag + k0 + lc);
        float4 w4 = *(const float4*)(Wg + k0 + lc);
        __syncthreads();   // previous iter's reads done
        As[lr][lc+0] = a4.x; As[lr][lc+1] = a4.y;
        As[lr][lc+2] = a4.z; As[lr][lc+3] = a4.w;
        Ws[lr][lc+0] = w4.x; Ws[lr][lc+1] = w4.y;
        Ws[lr][lc+2] = w4.z; Ws[lr][lc+3] = w4.w;
        __syncthreads();
#pragma unroll
        for (int kk = 0; kk < 16; kk++) {
            float a[4], b[4];
#pragma unroll
            for (int i = 0; i < 4; i++) a[i] = As[tr + 16*i][kk];
#pragma unroll
            for (int j = 0; j < 4; j++) b[j] = Ws[tc + 16*j][kk];
#pragma unroll
            for (int i = 0; i < 4; i++)
#pragma unroll
                for (int j = 0; j < 4; j++) acc[i][j] += a[i]*b[j];
        }
    }

#pragma unroll
    for (int i = 0; i < 4; i++) {
        const int row = bm*64 + tr + 16*i;      // token index
#pragma unroll
        for (int j = 0; j < 4; j++) {
            const int col = bn*64 + tc + 16*j;  // model dim
            const float v = (acc[i][j] + bias[col]) * scale;
            if (SPLIT) {
                const int bb = row >> 11;       // /SEQ
                const int ss = row & (SEQ-1);
                const int hh = col >> 6;        // /DH
                const int cc = col & (DH-1);
                out[(((size_t)bb*NH + hh)*SEQ + ss)*DH + cc] = v;
            } else {
                out[(size_t)row*DM + col] = v;
            }
        }
    }
}

// ---------------------------------------------------------------------------
// Flash attention: one CTA per (qtile=64 rows, h, b). fp32, online softmax.
// smem: Q,K,V,P tiles 64x65 (padded), m/l/alpha rows.
// ---------------------------------------------------------------------------
#define ATT_SMEM_FLOATS (4*64*65 + 3*64)
#define ATT_SMEM_BYTES  (ATT_SMEM_FLOATS*4)

__global__ __launch_bounds__(256, 3)
void attn_kernel(const float* __restrict__ Q, const float* __restrict__ K,
                 const float* __restrict__ V, float* __restrict__ out)
{
    extern __shared__ float sm[];
    float* Qs  = sm;                 // 64*65
    float* Ks  = Qs + 64*65;
    float* Vs  = Ks + 64*65;
    float* Ps  = Vs + 64*65;
    float* m_s = Ps + 64*65;         // 64
    float* l_s = m_s + 64;           // 64
    float* a_s = l_s + 64;           // 64

    const int tid = threadIdx.x;
    const int tr  = tid >> 4;
    const int tc  = tid & 15;
    const int qt  = blockIdx.x;      // 0..31
    const int h   = blockIdx.y;
    const int b   = blockIdx.z;

    const float* Qg = Q + (((size_t)b*NH + h)*SEQ + qt*64)*DH;
    const float* Kg = K + ((size_t)b*NH + h)*SEQ*DH;
    const float* Vg = V + ((size_t)b*NH + h)*SEQ*DH;

    // load Q tile (64x64) coalesced
#pragma unroll
    for (int it = 0; it < 4; it++) {
        const int idx = tid + it*256;          // 0..1023 float4 slots
        const int r   = idx >> 4;
        const int c4  = (idx & 15) * 4;
        const float4 t4 = *(const float4*)(Qg + r*DH + c4);
        float* dst = Qs + r*65 + c4;
        dst[0]=t4.x; dst[1]=t4.y; dst[2]=t4.z; dst[3]=t4.w;
    }
    if (tid < 64) { m_s[tid] = -1e30f; l_s[tid] = 0.f; }

    float o[4][4];
#pragma unroll
    for (int i = 0; i < 4; i++)
#pragma unroll
        for (int j = 0; j < 4; j++) o[i][j] = 0.f;

    for (int kt = 0; kt < SEQ/64; kt++) {
        const float* Kt = Kg + (size_t)kt*64*DH;
        const float* Vt = Vg + (size_t)kt*64*DH;

        __syncthreads();  // prior P@V reads of Ks/Vs/Ps complete
#pragma unroll
        for (int it = 0; it < 4; it++) {
            const int idx = tid + it*256;
            const int r   = idx >> 4;
            const int c4  = (idx & 15) * 4;
            float4 k4 = *(const float4*)(Kt + r*DH + c4);
            float4 v4 = *(const float4*)(Vt + r*DH + c4);
            float* kd = Ks + r*65 + c4;
            kd[0]=k4.x; kd[1]=k4.y; kd[2]=k4.z; kd[3]=k4.w;
            float* vd = Vs + r*65 + c4;
            vd[0]=v4.x; vd[1]=v4.y; vd[2]=v4.z; vd[3]=v4.w;
        }
        __syncthreads();  // tiles (and first-iter Qs, m/l init) visible

        // scores: S = Q_tile @ K_tile^T  (q already scaled by 1/8)
        float acc[4][4];
#pragma unroll
        for (int i = 0; i < 4; i++)
#pragma unroll
            for (int j = 0; j < 4; j++) acc[i][j] = 0.f;
#pragma unroll 8
        for (int kk = 0; kk < DH; kk++) {
            float a[4], bb[4];
#pragma unroll
            for (int i = 0; i < 4; i++) a[i]  = Qs[(tr + 16*i)*65 + kk];
#pragma unroll
            for (int j = 0; j < 4; j++) bb[j] = Ks[(tc + 16*j)*65 + kk];
#pragma unroll
            for (int i = 0; i < 4; i++)
#pragma unroll
                for (int j = 0; j < 4; j++) acc[i][j] += a[i]*bb[j];
        }
#pragma unroll
        for (int i = 0; i < 4; i++)
#pragma unroll
            for (int j = 0; j < 4; j++)
                Ps[(tr + 16*i)*65 + tc + 16*j] = acc[i][j];
        __syncthreads();

        // online softmax, one thread per row (threads 0..63)
        if (tid < 64) {
            const int r = tid;
            float* row = Ps + r*65;
            float mold = m_s[r];
            float rmax = -1e30f;
#pragma unroll 8
            for (int c = 0; c < 64; c++) rmax = fmaxf(rmax, row[c]);
            const float mnew  = fmaxf(mold, rmax);
            const float alpha = __expf(mold - mnew);
            float sum = 0.f;
#pragma unroll 8
            for (int c = 0; c < 64; c++) {
                const float p = __expf(row[c] - mnew);
                row[c] = p;
                sum += p;
            }
            l_s[r] = l_s[r]*alpha + sum;
            m_s[r] = mnew;
            a_s[r] = alpha;
        }
        __syncthreads();

        // rescale accumulator, then O += P @ V
        float al[4];
#pragma unroll
        for (int i = 0; i < 4; i++) al[i] = a_s[tr + 16*i];
#pragma unroll
        for (int i = 0; i < 4; i++)
#pragma unroll
            for (int j = 0; j < 4; j++) o[i][j] *= al[i];
#pragma unroll 8
        for (int kk = 0; kk < 64; kk++) {
            float a[4], bb[4];
#pragma unroll
            for (int i = 0; i < 4; i++) a[i]  = Ps[(tr + 16*i)*65 + kk];
#pragma unroll
            for (int j = 0; j < 4; j++) bb[j] = Vs[kk*65 + tc + 16*j];
#pragma unroll
            for (int i = 0; i < 4; i++)
#pragma unroll
                for (int j = 0; j < 4; j++) o[i][j] += a[i]*bb[j];
        }
    }

    // epilogue: divide by l, write [B,S,D] with heads merged
#pragma unroll
    for (int i = 0; i < 4; i++) {
        const int r   = tr + 16*i;
        const float inv = 1.0f / l_s[r];
        const int ss  = qt*64 + r;
#pragma unroll
        for (int j = 0; j < 4; j++) {
            const int cc = tc + 16*j;
            out[((size_t)(b*SEQ + ss))*DM + h*DH + cc] = o[i][j]*inv;
        }
    }
}

// ---------------------------------------------------------------------------
extern "C" void kernel_launch(void* const* d_in, const int* in_sizes, int n_in,
                              void* d_out, int out_size)
{
    const float* x  = (const float*)d_in[0];
    const float* Wq = (const float*)d_in[1];
    const float* bq = (const float*)d_in[2];
    const float* Wk = (const float*)d_in[3];
    const float* bk = (const float*)d_in[4];
    const float* Wv = (const float*)d_in[5];
    const float* bv = (const float*)d_in[6];
    const float* Wo = (const float*)d_in[7];
    const float* bo = (const float*)d_in[8];
    float* out = (float*)d_out;

    float *q, *k, *v, *att;
    cudaGetSymbolAddress((void**)&q,   g_q);
    cudaGetSymbolAddress((void**)&k,   g_k);
    cudaGetSymbolAddress((void**)&v,   g_v);
    cudaGetSymbolAddress((void**)&att, g_att);

    cudaFuncSetAttribute(attn_kernel,
                         cudaFuncAttributeMaxDynamicSharedMemorySize,
                         ATT_SMEM_BYTES);

    const dim3 pgrid(DM/64, NTOK/64);   // (8, 64)
    const float qscale = 1.0f / 8.0f;   // 1/sqrt(DH)

    proj_kernel<true><<<pgrid, 256>>>(x, Wq, bq, q, qscale);
    proj_kernel<true><<<pgrid, 256>>>(x, Wk, bk, k, 1.0f);
    proj_kernel<true><<<pgrid, 256>>>(x, Wv, bv, v, 1.0f);

    attn_kernel<<<dim3(SEQ/64, NH, BAT), 256, ATT_SMEM_BYTES>>>(q, k, v, att);

    proj_kernel<false><<<pgrid, 256>>>(att, Wo, bo, out, 1.0f);
}

// round 2
// speedup vs baseline: 3.6856x; 3.6856x over previous
#include <cuda_runtime.h>
#include <math.h>

#define DM   512
#define NH   8
#define DH   64
#define BAT  2
#define SEQ  2048
#define NTOK (BAT*SEQ)   // 4096

// Scratch (device globals; no allocations allowed)
__device__ float g_q[BAT*NH*SEQ*DH];     // [B,H,S,d], pre-scaled by 1/sqrt(d)
__device__ float g_k[BAT*NH*SEQ*DH];
__device__ float g_v[BAT*NH*SEQ*DH];
__device__ float g_att[NTOK*DM];         // attention output in [B,S,D]

// ---------------------------------------------------------------------------
// helpers
// ---------------------------------------------------------------------------
__device__ __forceinline__ unsigned f2tf(float f) {
    unsigned u;
    asm("cvt.rna.tf32.f32 %0, %1;" : "=r"(u) : "f"(f));
    return u;
}

// D = A@B + D, m16n8k8 tf32. a[4], b[2], c[4] per thread.
__device__ __forceinline__ void mma8(float* c, const unsigned* a, const unsigned* b) {
    asm volatile(
        "mma.sync.aligned.m16n8k8.row.col.f32.tf32.tf32.f32 "
        "{%0,%1,%2,%3}, {%4,%5,%6,%7}, {%8,%9}, {%0,%1,%2,%3};"
        : "+f"(c[0]), "+f"(c[1]), "+f"(c[2]), "+f"(c[3])
        : "r"(a[0]), "r"(a[1]), "r"(a[2]), "r"(a[3]), "r"(b[0]), "r"(b[1]));
}

// ---------------------------------------------------------------------------
// Projection GEMM: C[4096, 512] = A[4096,512] @ W[512,512]^T, (acc+bias)*scale
// Block tile 128x64, 8 warps (4 row x 2 col), warp tile 32x32, K-chunk 32.
// ---------------------------------------------------------------------------
#define PBM 128
#define PBN 64
#define PBK 32
#define PLD 36   // 36 % 32 == 4 -> conflict-free fragment loads

template<bool SPLIT>
__global__ __launch_bounds__(256)
void proj_mma(const float* __restrict__ A, const float* __restrict__ W,
              const float* __restrict__ bias, float* __restrict__ out,
              float scale)
{
    __shared__ unsigned As[PBM * PLD];
    __shared__ unsigned Bs[PBN * PLD];

    const int tid  = threadIdx.x;
    const int lane = tid & 31;
    const int wid  = tid >> 5;
    const int wr   = wid >> 1;      // 0..3
    const int wc   = wid & 1;       // 0..1
    const int g    = lane >> 2;     // 0..7
    const int t4   = lane & 3;      // 0..3
    const int bm   = blockIdx.y;
    const int bn   = blockIdx.x;

    const float* Ag = A + (size_t)bm * PBM * DM;
    const float* Wg = W + (size_t)bn * PBN * DM;

    float acc[2][4][4];
#pragma unroll
    for (int i = 0; i < 2; i++)
#pragma unroll
        for (int j = 0; j < 4; j++)
#pragma unroll
            for (int r = 0; r < 4; r++) acc[i][j][r] = 0.f;

    for (int k0 = 0; k0 < DM; k0 += PBK) {
        float4 ar[4], br[2];
#pragma unroll
        for (int i = 0; i < 4; i++) {
            const int idx = tid + i * 256;
            const int r = idx >> 3, q = idx & 7;
            ar[i] = *(const float4*)(Ag + (size_t)r * DM + k0 + q * 4);
        }
#pragma unroll
        for (int i = 0; i < 2; i++) {
            const int idx = tid + i * 256;
            const int r = idx >> 3, q = idx & 7;
            br[i] = *(const float4*)(Wg + (size_t)r * DM + k0 + q * 4);
        }
        __syncthreads();
#pragma unroll
        for (int i = 0; i < 4; i++) {
            const int idx = tid + i * 256;
            const int r = idx >> 3, q = idx & 7;
            unsigned* d = &As[r * PLD + q * 4];
            d[0] = f2tf(ar[i].x); d[1] = f2tf(ar[i].y);
            d[2] = f2tf(ar[i].z); d[3] = f2tf(ar[i].w);
        }
#pragma unroll
        for (int i = 0; i < 2; i++) {
            const int idx = tid + i * 256;
            const int r = idx >> 3, q = idx & 7;
            unsigned* d = &Bs[r * PLD + q * 4];
            d[0] = f2tf(br[i].x); d[1] = f2tf(br[i].y);
            d[2] = f2tf(br[i].z); d[3] = f2tf(br[i].w);
        }
        __syncthreads();

#pragma unroll
        for (int kk = 0; kk < PBK / 8; kk++) {
            const int kb = kk * 8;
            unsigned af[2][4], bf[4][2];
#pragma unroll
            for (int i = 0; i < 2; i++) {
                const unsigned* base = &As[(wr * 32 + i * 16) * PLD + kb];
                af[i][0] = base[g * PLD + t4];
                af[i][1] = base[(g + 8) * PLD + t4];
                af[i][2] = base[g * PLD + t4 + 4];
                af[i][3] = base[(g + 8) * PLD + t4 + 4];
            }
#pragma unroll
            for (int j = 0; j < 4; j++) {
                const unsigned* base = &Bs[(wc * 32 + j * 8) * PLD + kb];
                bf[j][0] = base[g * PLD + t4];
                bf[j][1] = base[g * PLD + t4 + 4];
            }
#pragma unroll
            for (int i = 0; i < 2; i++)
#pragma unroll
                for (int j = 0; j < 4; j++) mma8(acc[i][j], af[i], bf[j]);
        }
    }

    // epilogue: c0 (g,2t4) c1 (g,2t4+1) c2 (g+8,2t4) c3 (g+8,2t4+1)
#pragma unroll
    for (int i = 0; i < 2; i++) {
        const int row0 = bm * PBM + wr * 32 + i * 16 + g;
        const int row1 = row0 + 8;
#pragma unroll
        for (int j = 0; j < 4; j++) {
            const int col0 = bn * PBN + wc * 32 + j * 8 + 2 * t4;
            const float v00 = (acc[i][j][0] + bias[col0])     * scale;
            const float v01 = (acc[i][j][1] + bias[col0 + 1]) * scale;
            const float v10 = (acc[i][j][2] + bias[col0])     * scale;
            const float v11 = (acc[i][j][3] + bias[col0 + 1]) * scale;
            if (SPLIT) {
                const int b0 = row0 >> 11, s0 = row0 & (SEQ - 1);
                const int b1 = row1 >> 11, s1 = row1 & (SEQ - 1);
                const int hh = col0 >> 6,  cc = col0 & (DH - 1);
                out[(((size_t)b0 * NH + hh) * SEQ + s0) * DH + cc]     = v00;
                out[(((size_t)b0 * NH + hh) * SEQ + s0) * DH + cc + 1] = v01;
                out[(((size_t)b1 * NH + hh) * SEQ + s1) * DH + cc]     = v10;
                out[(((size_t)b1 * NH + hh) * SEQ + s1) * DH + cc + 1] = v11;
            } else {
                out[(size_t)row0 * DM + col0]     = v00;
                out[(size_t)row0 * DM + col0 + 1] = v01;
                out[(size_t)row1 * DM + col0]     = v10;
                out[(size_t)row1 * DM + col0 + 1] = v11;
            }
        }
    }
}

// ---------------------------------------------------------------------------
// Flash attention, tf32 mma. Br=128, Bc=64. 8 warps (4x2), warp tile 32x32.
// ---------------------------------------------------------------------------
#define ALDQ 68   // 68 % 32 == 4 : A-pattern conflict-free
#define ALDK 68
#define ALDV 72   // 72 % 32 == 8 : B-pattern conflict-free
#define ALDP 68
#define ATT_SMEM_WORDS (128*ALDQ + 64*ALDK + 64*ALDV + 128*ALDP + 3*128)
#define ATT_SMEM_BYTES (ATT_SMEM_WORDS * 4)

__global__ __launch_bounds__(256)
void attn_mma(const float* __restrict__ Q, const float* __restrict__ K,
              const float* __restrict__ V, float* __restrict__ out)
{
    extern __shared__ unsigned sm[];
    unsigned* Qs = sm;                       // 128 x ALDQ (tf32)
    unsigned* Ks = Qs + 128 * ALDQ;          // 64 x ALDK (tf32)
    unsigned* Vs = Ks + 64 * ALDK;           // 64 x ALDV (tf32)
    unsigned* Ps = Vs + 64 * ALDV;           // 128 x ALDP (fp32 scores -> tf32 probs)
    float* m_s = (float*)(Ps + 128 * ALDP);  // 128
    float* l_s = m_s + 128;
    float* a_s = l_s + 128;

    const int tid  = threadIdx.x;
    const int lane = tid & 31;
    const int wid  = tid >> 5;
    const int wr   = wid >> 1;      // 0..3
    const int wc   = wid & 1;       // 0..1
    const int g    = lane >> 2;
    const int t4   = lane & 3;
    const int qt   = blockIdx.x;
    const int h    = blockIdx.y;
    const int b    = blockIdx.z;

    const float* Qg = Q + (((size_t)b * NH + h) * SEQ + qt * 128) * DH;
    const float* Kg = K + ((size_t)b * NH + h) * SEQ * DH;
    const float* Vg = V + ((size_t)b * NH + h) * SEQ * DH;

    // Q tile: 128x64 -> 2048 float4
#pragma unroll
    for (int i = 0; i < 8; i++) {
        const int idx = tid + i * 256;
        const int r = idx >> 4, q = idx & 15;
        const float4 v4 = *(const float4*)(Qg + r * DH + q * 4);
        unsigned* d = &Qs[r * ALDQ + q * 4];
        d[0] = f2tf(v4.x); d[1] = f2tf(v4.y); d[2] = f2tf(v4.z); d[3] = f2tf(v4.w);
    }
    if (tid < 128) { m_s[tid] = -1e30f; l_s[tid] = 0.f; }

    float o[2][4][4];
#pragma unroll
    for (int i = 0; i < 2; i++)
#pragma unroll
        for (int j = 0; j < 4; j++)
#pragma unroll
            for (int r = 0; r < 4; r++) o[i][j][r] = 0.f;

    for (int kt = 0; kt < SEQ / 64; kt++) {
        const float* Kt = Kg + (size_t)kt * 64 * DH;
        const float* Vt = Vg + (size_t)kt * 64 * DH;

        __syncthreads();   // prev iter's reads of Ks/Vs done
#pragma unroll
        for (int i = 0; i < 4; i++) {
            const int idx = tid + i * 256;
            const int r = idx >> 4, q = idx & 15;
            const float4 k4 = *(const float4*)(Kt + r * DH + q * 4);
            const float4 v4 = *(const float4*)(Vt + r * DH + q * 4);
            unsigned* kd = &Ks[r * ALDK + q * 4];
            kd[0] = f2tf(k4.x); kd[1] = f2tf(k4.y); kd[2] = f2tf(k4.z); kd[3] = f2tf(k4.w);
            unsigned* vd = &Vs[r * ALDV + q * 4];
            vd[0] = f2tf(v4.x); vd[1] = f2tf(v4.y); vd[2] = f2tf(v4.z); vd[3] = f2tf(v4.w);
        }
        __syncthreads();

        // S = Q @ K^T   (warp tile 32x32)
        float s[2][4][4];
#pragma unroll
        for (int i = 0; i < 2; i++)
#pragma unroll
            for (int j = 0; j < 4; j++)
#pragma unroll
                for (int r = 0; r < 4; r++) s[i][j][r] = 0.f;
#pragma unroll
        for (int kk = 0; kk < 8; kk++) {
            const int kb = kk * 8;
            unsigned af[2][4], bf[4][2];
#pragma unroll
            for (int i = 0; i < 2; i++) {
                const unsigned* base = &Qs[(wr * 32 + i * 16) * ALDQ + kb];
                af[i][0] = base[g * ALDQ + t4];
                af[i][1] = base[(g + 8) * ALDQ + t4];
                af[i][2] = base[g * ALDQ + t4 + 4];
                af[i][3] = base[(g + 8) * ALDQ + t4 + 4];
            }
#pragma unroll
            for (int j = 0; j < 4; j++) {
                const unsigned* base = &Ks[(wc * 32 + j * 8) * ALDK + kb];
                bf[j][0] = base[g * ALDK + t4];
                bf[j][1] = base[g * ALDK + t4 + 4];
            }
#pragma unroll
            for (int i = 0; i < 2; i++)
#pragma unroll
                for (int j = 0; j < 4; j++) mma8(s[i][j], af[i], bf[j]);
        }

        // store fp32 scores
#pragma unroll
        for (int i = 0; i < 2; i++) {
            const int row = wr * 32 + i * 16;
#pragma unroll
            for (int j = 0; j < 4; j++) {
                const int col = wc * 32 + j * 8 + 2 * t4;
                unsigned* p0 = &Ps[(row + g) * ALDP + col];
                p0[0] = __float_as_uint(s[i][j][0]);
                p0[1] = __float_as_uint(s[i][j][1]);
                unsigned* p1 = &Ps[(row + g + 8) * ALDP + col];
                p1[0] = __float_as_uint(s[i][j][2]);
                p1[1] = __float_as_uint(s[i][j][3]);
            }
        }
        __syncthreads();

        // online softmax: 2 threads per row
        {
            const int r  = tid >> 1;
            const int hf = tid & 1;
            float* row = (float*)&Ps[r * ALDP + hf * 32];
            const float mold = m_s[r];
            float lm = -1e30f;
#pragma unroll
            for (int c = 0; c < 32; c++) lm = fmaxf(lm, row[c]);
            lm = fmaxf(lm, __shfl_xor_sync(0xffffffffu, lm, 1));
            const float mnew  = fmaxf(mold, lm);
            const float alpha = __expf(mold - mnew);
            float sum = 0.f;
#pragma unroll
            for (int c = 0; c < 32; c++) {
                const float p = __expf(row[c] - mnew);
                sum += p;
                ((unsigned*)row)[c] = f2tf(p);
            }
            sum += __shfl_xor_sync(0xffffffffu, sum, 1);
            if (hf == 0) {
                m_s[r] = mnew;
                l_s[r] = l_s[r] * alpha + sum;
                a_s[r] = alpha;
            }
        }
        __syncthreads();

        // rescale O, then O += P @ V
        float al0[2], al1[2];
#pragma unroll
        for (int i = 0; i < 2; i++) {
            al0[i] = a_s[wr * 32 + i * 16 + g];
            al1[i] = a_s[wr * 32 + i * 16 + g + 8];
        }
#pragma unroll
        for (int i = 0; i < 2; i++)
#pragma unroll
            for (int j = 0; j < 4; j++) {
                o[i][j][0] *= al0[i]; o[i][j][1] *= al0[i];
                o[i][j][2] *= al1[i]; o[i][j][3] *= al1[i];
            }
#pragma unroll
        for (int kk = 0; kk < 8; kk++) {
            const int kb = kk * 8;
            unsigned af[2][4], bf[4][2];
#pragma unroll
            for (int i = 0; i < 2; i++) {
                const unsigned* base = &Ps[(wr * 32 + i * 16) * ALDP + kb];
                af[i][0] = base[g * ALDP + t4];
                af[i][1] = base[(g + 8) * ALDP + t4];
                af[i][2] = base[g * ALDP + t4 + 4];
                af[i][3] = base[(g + 8) * ALDP + t4 + 4];
            }
#pragma unroll
            for (int j = 0; j < 4; j++) {
                const int nb = wc * 32 + j * 8;
                bf[j][0] = Vs[(kb + t4) * ALDV + nb + g];
                bf[j][1] = Vs[(kb + t4 + 4) * ALDV + nb + g];
            }
#pragma unroll
            for (int i = 0; i < 2; i++)
#pragma unroll
                for (int j = 0; j < 4; j++) mma8(o[i][j], af[i], bf[j]);
        }
    }

    // epilogue: divide by l, write [B,S,D]
#pragma unroll
    for (int i = 0; i < 2; i++) {
        const int r0 = wr * 32 + i * 16 + g;
        const int r1 = r0 + 8;
        const float inv0 = 1.f / l_s[r0];
        const float inv1 = 1.f / l_s[r1];
        const int s0 = qt * 128 + r0;
        const int s1 = qt * 128 + r1;
#pragma unroll
        for (int j = 0; j < 4; j++) {
            const int col = h * DH + wc * 32 + j * 8 + 2 * t4;
            float* o0 = &out[((size_t)(b * SEQ + s0)) * DM + col];
            o0[0] = o[i][j][0] * inv0;
            o0[1] = o[i][j][1] * inv0;
            float* o1 = &out[((size_t)(b * SEQ + s1)) * DM + col];
            o1[0] = o[i][j][2] * inv1;
            o1[1] = o[i][j][3] * inv1;
        }
    }
}

// ---------------------------------------------------------------------------
extern "C" void kernel_launch(void* const* d_in, const int* in_sizes, int n_in,
                              void* d_out, int out_size)
{
    const float* x  = (const float*)d_in[0];
    const float* Wq = (const float*)d_in[1];
    const float* bq = (const float*)d_in[2];
    const float* Wk = (const float*)d_in[3];
    const float* bk = (const float*)d_in[4];
    const float* Wv = (const float*)d_in[5];
    const float* bv = (const float*)d_in[6];
    const float* Wo = (const float*)d_in[7];
    const float* bo = (const float*)d_in[8];
    float* out = (float*)d_out;

    float *q, *k, *v, *att;
    cudaGetSymbolAddress((void**)&q,   g_q);
    cudaGetSymbolAddress((void**)&k,   g_k);
    cudaGetSymbolAddress((void**)&v,   g_v);
    cudaGetSymbolAddress((void**)&att, g_att);

    cudaFuncSetAttribute(attn_mma,
                         cudaFuncAttributeMaxDynamicSharedMemorySize,
                         ATT_SMEM_BYTES);

    const dim3 pgrid(DM / PBN, NTOK / PBM);   // (8, 32)
    const float qscale = 1.0f / 8.0f;         // 1/sqrt(DH)

    proj_mma<true><<<pgrid, 256>>>(x, Wq, bq, q, qscale);
    proj_mma<true><<<pgrid, 256>>>(x, Wk, bk, k, 1.0f);
    proj_mma<true><<<pgrid, 256>>>(x, Wv, bv, v, 1.0f);

    attn_mma<<<dim3(SEQ / 128, NH, BAT), 256, ATT_SMEM_BYTES>>>(q, k, v, att);

    proj_mma<false><<<pgrid, 256>>>(att, Wo, bo, out, 1.0f);
}

// round 3
// speedup vs baseline: 4.4169x; 1.1984x over previous
#include <cuda_runtime.h>
#include <math.h>
#include <stdint.h>

#define DM   512
#define NH   8
#define DH   64
#define BAT  2
#define SEQ  2048
#define NTOK (BAT*SEQ)   // 4096

// Scratch (device globals)
__device__ float g_q[BAT*NH*SEQ*DH];     // [B,H,S,d], pre-scaled by 1/8
__device__ float g_k[BAT*NH*SEQ*DH];     // [B,H,S,d]
__device__ float g_vt[BAT*NH*DH*SEQ];    // V TRANSPOSED: [B,H,d,S]
__device__ float g_att[NTOK*DM];         // attention output [B,S,D]

// ---------------------------------------------------------------------------
// helpers
// ---------------------------------------------------------------------------
__device__ __forceinline__ unsigned f2tf(float f) {
    unsigned u;
    asm("cvt.rna.tf32.f32 %0, %1;" : "=r"(u) : "f"(f));
    return u;
}

__device__ __forceinline__ void mma8(float* c, const unsigned* a, const unsigned* b) {
    asm volatile(
        "mma.sync.aligned.m16n8k8.row.col.f32.tf32.tf32.f32 "
        "{%0,%1,%2,%3}, {%4,%5,%6,%7}, {%8,%9}, {%0,%1,%2,%3};"
        : "+f"(c[0]), "+f"(c[1]), "+f"(c[2]), "+f"(c[3])
        : "r"(a[0]), "r"(a[1]), "r"(a[2]), "r"(a[3]), "r"(b[0]), "r"(b[1]));
}

__device__ __forceinline__ void ldsm4(unsigned* r, uint32_t addr) {
    asm volatile("ldmatrix.sync.aligned.m8n8.x4.shared.b16 {%0,%1,%2,%3}, [%4];"
        : "=r"(r[0]), "=r"(r[1]), "=r"(r[2]), "=r"(r[3]) : "r"(addr));
}

// ---------------------------------------------------------------------------
// Projection GEMM: C[4096,512] = A[4096,512] @ W[512,512]^T, (acc+bias)*scale
// MODE: 0 = flat [B,S,D], 1 = split heads [B,H,S,d], 2 = V transposed [B,H,d,S]
// 128x64 block tile, 8 warps (4 row x 2 col), warp tile 32x32, K-chunk 32.
// ---------------------------------------------------------------------------
#define PBM 128
#define PBN 64
#define PBK 32
#define PLD 36      // 36 % 32 == 4 -> conflict-free ldmatrix rows
#define TLD 132     // transpose stage leading dim

#define PROJ_SMEM_STD   ((PBM*PLD + PBN*PLD) * 4)      // 27648 B
#define PROJ_SMEM_TRV   (64 * TLD * 4)                 // 33792 B

template<int MODE>
__global__ __launch_bounds__(256)
void proj_mma(const float* __restrict__ A, const float* __restrict__ W,
              const float* __restrict__ bias, float* __restrict__ out,
              float scale)
{
    extern __shared__ unsigned psm[];
    unsigned* As = psm;
    unsigned* Bs = psm + PBM * PLD;

    const int tid  = threadIdx.x;
    const int lane = tid & 31;
    const int wid  = tid >> 5;
    const int wr   = wid >> 1;      // 0..3
    const int wc   = wid & 1;       // 0..1
    const int g    = lane >> 2;     // 0..7
    const int t4   = lane & 3;      // 0..3
    const int bm   = blockIdx.y;
    const int bn   = blockIdx.x;

    const float* Ag = A + (size_t)bm * PBM * DM;
    const float* Wg = W + (size_t)bn * PBN * DM;

    const uint32_t sb = (uint32_t)__cvta_generic_to_shared(psm);
    const int lr7 = lane & 7, lb3 = (lane >> 3) & 1, lb4 = (lane >> 4) & 1;
    // A fragment ldmatrix base (per 16-row tile i)
    uint32_t aAddr[2];
#pragma unroll
    for (int i = 0; i < 2; i++)
        aAddr[i] = sb + ((wr*32 + i*16 + lr7 + lb3*8) * PLD + lb4*4) * 4;
    // B fragment ldmatrix base (per pair of 8-row n-tiles jj)
    uint32_t bAddr[2];
#pragma unroll
    for (int jj = 0; jj < 2; jj++)
        bAddr[jj] = sb + (PBM*PLD + (wc*32 + jj*16 + lr7 + lb4*8) * PLD + lb3*4) * 4;

    float acc[2][4][4];
#pragma unroll
    for (int i = 0; i < 2; i++)
#pragma unroll
        for (int j = 0; j < 4; j++)
#pragma unroll
            for (int r = 0; r < 4; r++) acc[i][j][r] = 0.f;

    for (int k0 = 0; k0 < DM; k0 += PBK) {
        float4 ar[4], br[2];
#pragma unroll
        for (int i = 0; i < 4; i++) {
            const int idx = tid + i * 256;
            const int r = idx >> 3, q = idx & 7;
            ar[i] = *(const float4*)(Ag + (size_t)r * DM + k0 + q * 4);
        }
#pragma unroll
        for (int i = 0; i < 2; i++) {
            const int idx = tid + i * 256;
            const int r = idx >> 3, q = idx & 7;
            br[i] = *(const float4*)(Wg + (size_t)r * DM + k0 + q * 4);
        }
        __syncthreads();
#pragma unroll
        for (int i = 0; i < 4; i++) {
            const int idx = tid + i * 256;
            const int r = idx >> 3, q = idx & 7;
            uint4 u;
            u.x = f2tf(ar[i].x); u.y = f2tf(ar[i].y);
            u.z = f2tf(ar[i].z); u.w = f2tf(ar[i].w);
            *(uint4*)&As[r * PLD + q * 4] = u;
        }
#pragma unroll
        for (int i = 0; i < 2; i++) {
            const int idx = tid + i * 256;
            const int r = idx >> 3, q = idx & 7;
            uint4 u;
            u.x = f2tf(br[i].x); u.y = f2tf(br[i].y);
            u.z = f2tf(br[i].z); u.w = f2tf(br[i].w);
            *(uint4*)&Bs[r * PLD + q * 4] = u;
        }
        __syncthreads();

#pragma unroll
        for (int kk = 0; kk < PBK / 8; kk++) {
            unsigned af[2][4], bf[2][4];
            ldsm4(af[0], aAddr[0] + kk * 32);
            ldsm4(af[1], aAddr[1] + kk * 32);
            ldsm4(bf[0], bAddr[0] + kk * 32);
            ldsm4(bf[1], bAddr[1] + kk * 32);
#pragma unroll
            for (int i = 0; i < 2; i++) {
                mma8(acc[i][0], af[i], bf[0]);
                mma8(acc[i][1], af[i], bf[0] + 2);
                mma8(acc[i][2], af[i], bf[1]);
                mma8(acc[i][3], af[i], bf[1] + 2);
            }
        }
    }

    if (MODE == 2) {
        // stage (bias-added) tile transposed in smem, then coalesced write
        float* Ts = (float*)psm;
        __syncthreads();
#pragma unroll
        for (int i = 0; i < 2; i++) {
            const int ss = wr*32 + i*16 + g;
#pragma unroll
            for (int j = 0; j < 4; j++) {
                const int cc = wc*32 + j*8 + 2*t4;
                const float b0 = bias[bn*PBN + cc], b1 = bias[bn*PBN + cc + 1];
                Ts[cc * TLD + ss]           = acc[i][j][0] + b0;
                Ts[(cc + 1) * TLD + ss]     = acc[i][j][1] + b1;
                Ts[cc * TLD + ss + 8]       = acc[i][j][2] + b0;
                Ts[(cc + 1) * TLD + ss + 8] = acc[i][j][3] + b1;
            }
        }
        __syncthreads();
        const int bb = bm >> 4;
        const int sbase = (bm & 15) * 128;
        float* vout = out + (((size_t)bb * NH + bn) * DH) * SEQ;
#pragma unroll
        for (int t = 0; t < 8; t++) {
            const int idx = tid + t * 256;     // 2048 float4 slots
            const int cc = idx >> 5;
            const int sl = (idx & 31) * 4;
            float4 val = *(float4*)&Ts[cc * TLD + sl];
            *(float4*)(vout + (size_t)cc * SEQ + sbase + sl) = val;
        }
        return;
    }

#pragma unroll
    for (int i = 0; i < 2; i++) {
        const int row0 = bm * PBM + wr * 32 + i * 16 + g;
        const int row1 = row0 + 8;
#pragma unroll
        for (int j = 0; j < 4; j++) {
            const int col0 = bn * PBN + wc * 32 + j * 8 + 2 * t4;
            const float v00 = (acc[i][j][0] + bias[col0])     * scale;
            const float v01 = (acc[i][j][1] + bias[col0 + 1]) * scale;
            const float v10 = (acc[i][j][2] + bias[col0])     * scale;
            const float v11 = (acc[i][j][3] + bias[col0 + 1]) * scale;
            if (MODE == 1) {
                const int b0 = row0 >> 11, s0 = row0 & (SEQ - 1);
                const int b1 = row1 >> 11, s1 = row1 & (SEQ - 1);
                const int hh = col0 >> 6,  cc = col0 & (DH - 1);
                float* p0 = &((float*)out)[(((size_t)b0 * NH + hh) * SEQ + s0) * DH + cc];
                p0[0] = v00; p0[1] = v01;
                float* p1 = &((float*)out)[(((size_t)b1 * NH + hh) * SEQ + s1) * DH + cc];
                p1[0] = v10; p1[1] = v11;
            } else {
                float* p0 = &out[(size_t)row0 * DM + col0];
                p0[0] = v00; p0[1] = v01;
                float* p1 = &out[(size_t)row1 * DM + col0];
                p1[0] = v10; p1[1] = v11;
            }
        }
    }
}

// ---------------------------------------------------------------------------
// Flash attention, tf32 mma + ldmatrix. Br=128, Bc=64.
// 8 warps x 16 rows each (warp owns full rows -> in-register softmax).
// smem: Qs[128x68], Ks[64x68], Vs(=V^T)[64x68], Ps[128x68]  (tf32 words)
// ---------------------------------------------------------------------------
#define ALD 68
#define ATT_SMEM_BYTES ((128 + 64 + 64 + 128) * ALD * 4)   // 104448

__global__ __launch_bounds__(256, 2)
void attn_mma(const float* __restrict__ Q, const float* __restrict__ K,
              const float* __restrict__ VT, float* __restrict__ out)
{
    extern __shared__ unsigned sm[];
    unsigned* Qs = sm;                 // 128*ALD
    unsigned* Ks = Qs + 128 * ALD;     // 64*ALD
    unsigned* Vs = Ks + 64 * ALD;      // 64*ALD  (transposed V: [dh][tok])
    unsigned* Ps = Vs + 64 * ALD;      // 128*ALD

    const int tid  = threadIdx.x;
    const int lane = tid & 31;
    const int wid  = tid >> 5;
    const int wrow = wid * 16;
    const int g    = lane >> 2;
    const int t4   = lane & 3;
    const int qt   = blockIdx.x;
    const int h    = blockIdx.y;
    const int b    = blockIdx.z;

    const float* Qg  = Q  + (((size_t)b * NH + h) * SEQ + qt * 128) * DH;
    const float* Kg  = K  + ((size_t)b * NH + h) * SEQ * DH;
    const float* Vg  = VT + ((size_t)b * NH + h) * DH * SEQ;   // [dh][tok]

    const uint32_t sb = (uint32_t)__cvta_generic_to_shared(sm);
    const uint32_t kbB = sb + 128 * ALD * 4;
    const uint32_t vbB = kbB + 64 * ALD * 4;
    const uint32_t pbB = vbB + 64 * ALD * 4;

    const int lr7 = lane & 7, lb3 = (lane >> 3) & 1, lb4 = (lane >> 4) & 1;
    const uint32_t aQ0 = sb  + ((wrow + lr7 + lb3 * 8) * ALD + lb4 * 4) * 4;
    const uint32_t aP0 = pbB + ((wrow + lr7 + lb3 * 8) * ALD + lb4 * 4) * 4;
    const uint32_t bK0 = kbB + ((lr7 + lb4 * 8) * ALD + lb3 * 4) * 4;
    const uint32_t bV0 = vbB + ((lr7 + lb4 * 8) * ALD + lb3 * 4) * 4;

    const int r16 = tid >> 4, q16 = tid & 15;

    // load Q tile (128x64), cvt to tf32
#pragma unroll
    for (int i = 0; i < 8; i++) {
        const int rr = r16 + i * 16;
        float4 v4 = *(const float4*)(Qg + rr * DH + q16 * 4);
        uint4 u;
        u.x = f2tf(v4.x); u.y = f2tf(v4.y); u.z = f2tf(v4.z); u.w = f2tf(v4.w);
        *(uint4*)&Qs[rr * ALD + q16 * 4] = u;
    }

    float o[8][4];
#pragma unroll
    for (int j = 0; j < 8; j++)
#pragma unroll
        for (int r = 0; r < 4; r++) o[j][r] = 0.f;
    float mA = -1e30f, mB = -1e30f, lA = 0.f, lB = 0.f;

    for (int kt = 0; kt < SEQ / 64; kt++) {
        const float* Kt = Kg + (size_t)kt * 64 * DH;
        const float* Vt = Vg + kt * 64;
        float4 kr[4], vr[4];
#pragma unroll
        for (int i = 0; i < 4; i++) {
            kr[i] = *(const float4*)(Kt + (r16 + i * 16) * DH + q16 * 4);
            vr[i] = *(const float4*)(Vt + (size_t)(r16 + i * 16) * SEQ + q16 * 4);
        }
        __syncthreads();   // prior iter's fragment loads done
#pragma unroll
        for (int i = 0; i < 4; i++) {
            uint4 ku, vu;
            ku.x = f2tf(kr[i].x); ku.y = f2tf(kr[i].y);
            ku.z = f2tf(kr[i].z); ku.w = f2tf(kr[i].w);
            vu.x = f2tf(vr[i].x); vu.y = f2tf(vr[i].y);
            vu.z = f2tf(vr[i].z); vu.w = f2tf(vr[i].w);
            *(uint4*)&Ks[(r16 + i * 16) * ALD + q16 * 4] = ku;
            *(uint4*)&Vs[(r16 + i * 16) * ALD + q16 * 4] = vu;
        }
        __syncthreads();

        // S = Q @ K^T : warp computes its 16 rows x 64 cols
        float s[8][4];
#pragma unroll
        for (int j = 0; j < 8; j++)
#pragma unroll
            for (int r = 0; r < 4; r++) s[j][r] = 0.f;
#pragma unroll
        for (int kk = 0; kk < 8; kk++) {
            unsigned aq[4];
            ldsm4(aq, aQ0 + kk * 32);
#pragma unroll
            for (int jj = 0; jj < 4; jj++) {
                unsigned bk[4];
                ldsm4(bk, bK0 + jj * (16 * ALD * 4) + kk * 32);
                mma8(s[2 * jj],     aq, bk);
                mma8(s[2 * jj + 1], aq, bk + 2);
            }
        }

        // in-register online softmax (rows g / g+8, quad shfl over t4)
        float mxA = -1e30f, mxB = -1e30f;
#pragma unroll
        for (int j = 0; j < 8; j++) {
            mxA = fmaxf(mxA, fmaxf(s[j][0], s[j][1]));
            mxB = fmaxf(mxB, fmaxf(s[j][2], s[j][3]));
        }
        mxA = fmaxf(mxA, __shfl_xor_sync(0xffffffffu, mxA, 1));
        mxA = fmaxf(mxA, __shfl_xor_sync(0xffffffffu, mxA, 2));
        mxB = fmaxf(mxB, __shfl_xor_sync(0xffffffffu, mxB, 1));
        mxB = fmaxf(mxB, __shfl_xor_sync(0xffffffffu, mxB, 2));
        const float mnA = fmaxf(mA, mxA), mnB = fmaxf(mB, mxB);
        const float alA = __expf(mA - mnA), alB = __expf(mB - mnB);
        float suA = 0.f, suB = 0.f;
#pragma unroll
        for (int j = 0; j < 8; j++) {
            const float e0 = __expf(s[j][0] - mnA);
            const float e1 = __expf(s[j][1] - mnA);
            const float e2 = __expf(s[j][2] - mnB);
            const float e3 = __expf(s[j][3] - mnB);
            suA += e0 + e1;  suB += e2 + e3;
            s[j][0] = __uint_as_float(f2tf(e0));
            s[j][1] = __uint_as_float(f2tf(e1));
            s[j][2] = __uint_as_float(f2tf(e2));
            s[j][3] = __uint_as_float(f2tf(e3));
        }
        suA += __shfl_xor_sync(0xffffffffu, suA, 1);
        suA += __shfl_xor_sync(0xffffffffu, suA, 2);
        suB += __shfl_xor_sync(0xffffffffu, suB, 1);
        suB += __shfl_xor_sync(0xffffffffu, suB, 2);
        lA = lA * alA + suA;  mA = mnA;
        lB = lB * alB + suB;  mB = mnB;

        // rescale O
#pragma unroll
        for (int j = 0; j < 8; j++) {
            o[j][0] *= alA; o[j][1] *= alA;
            o[j][2] *= alB; o[j][3] *= alB;
        }

        // write P (warp-local), read back as A-fragments
        __syncwarp();
#pragma unroll
        for (int j = 0; j < 8; j++) {
            uint2 u0, u1;
            u0.x = __float_as_uint(s[j][0]); u0.y = __float_as_uint(s[j][1]);
            u1.x = __float_as_uint(s[j][2]); u1.y = __float_as_uint(s[j][3]);
            *(uint2*)&Ps[(wrow + g)     * ALD + j * 8 + 2 * t4] = u0;
            *(uint2*)&Ps[(wrow + g + 8) * ALD + j * 8 + 2 * t4] = u1;
        }
        __syncwarp();

        // O += P @ V   (V transposed in smem: b-frags via ldmatrix)
#pragma unroll
        for (int kc = 0; kc < 8; kc++) {
            unsigned ap[4];
            ldsm4(ap, aP0 + kc * 32);
#pragma unroll
            for (int jj = 0; jj < 4; jj++) {
                unsigned bv[4];
                ldsm4(bv, bV0 + jj * (16 * ALD * 4) + kc * 32);
                mma8(o[2 * jj],     ap, bv);
                mma8(o[2 * jj + 1], ap, bv + 2);
            }
        }
    }

    // epilogue
    const float invA = 1.f / lA, invB = 1.f / lB;
    const int rA = qt * 128 + wrow + g;
    float* oA = out + ((size_t)(b * SEQ + rA)) * DM + h * DH;
    float* oB = oA + (size_t)8 * DM;
#pragma unroll
    for (int j = 0; j < 8; j++) {
        const int col = j * 8 + 2 * t4;
        float2 vA, vB;
        vA.x = o[j][0] * invA; vA.y = o[j][1] * invA;
        vB.x = o[j][2] * invB; vB.y = o[j][3] * invB;
        *(float2*)(oA + col) = vA;
        *(float2*)(oB + col) = vB;
    }
}

// ---------------------------------------------------------------------------
extern "C" void kernel_launch(void* const* d_in, const int* in_sizes, int n_in,
                              void* d_out, int out_size)
{
    const float* x  = (const float*)d_in[0];
    const float* Wq = (const float*)d_in[1];
    const float* bq = (const float*)d_in[2];
    const float* Wk = (const float*)d_in[3];
    const float* bk = (const float*)d_in[4];
    const float* Wv = (const float*)d_in[5];
    const float* bv = (const float*)d_in[6];
    const float* Wo = (const float*)d_in[7];
    const float* bo = (const float*)d_in[8];
    float* out = (float*)d_out;

    float *q, *k, *vt, *att;
    cudaGetSymbolAddress((void**)&q,   g_q);
    cudaGetSymbolAddress((void**)&k,   g_k);
    cudaGetSymbolAddress((void**)&vt,  g_vt);
    cudaGetSymbolAddress((void**)&att, g_att);

    cudaFuncSetAttribute(attn_mma,
                         cudaFuncAttributeMaxDynamicSharedMemorySize,
                         ATT_SMEM_BYTES);

    const dim3 pgrid(DM / PBN, NTOK / PBM);   // (8, 32)
    const float qscale = 1.0f / 8.0f;         // 1/sqrt(DH)

    proj_mma<1><<<pgrid, 256, PROJ_SMEM_STD>>>(x, Wq, bq, q,  qscale);
    proj_mma<1><<<pgrid, 256, PROJ_SMEM_STD>>>(x, Wk, bk, k,  1.0f);
    proj_mma<2><<<pgrid, 256, PROJ_SMEM_TRV>>>(x, Wv, bv, vt, 1.0f);

    attn_mma<<<dim3(SEQ / 128, NH, BAT), 256, ATT_SMEM_BYTES>>>(q, k, vt, att);

    proj_mma<0><<<pgrid, 256, PROJ_SMEM_STD>>>(att, Wo, bo, out, 1.0f);
}

// round 5
// speedup vs baseline: 4.6185x; 1.0456x over previous
#include <cuda_runtime.h>
#include <math.h>
#include <stdint.h>

#define DM   512
#define NH   8
#define DH   64
#define BAT  2
#define SEQ  2048
#define NTOK (BAT*SEQ)   // 4096

// Scratch (device globals)
__device__ float g_x[NTOK*DM];           // x pre-rounded to tf32
__device__ float g_w[4*DM*DM];           // Wq,Wk,Wv,Wo pre-rounded to tf32
__device__ float g_q[BAT*NH*SEQ*DH];     // [B,H,S,d], pre-scaled by 1/8, tf32
__device__ float g_k[BAT*NH*SEQ*DH];     // [B,H,S,d], tf32
__device__ float g_vt[BAT*NH*DH*SEQ];    // V TRANSPOSED [B,H,d,S], tf32
__device__ float g_att[NTOK*DM];         // attention output [B,S,D], tf32

// ---------------------------------------------------------------------------
// helpers
// ---------------------------------------------------------------------------
__device__ __forceinline__ unsigned f2tf(float f) {
    unsigned u;
    asm("cvt.rna.tf32.f32 %0, %1;" : "=r"(u) : "f"(f));
    return u;
}
__device__ __forceinline__ float rtf(float f) { return __uint_as_float(f2tf(f)); }

__device__ __forceinline__ void mma8(float* c, const unsigned* a, const unsigned* b) {
    asm volatile(
        "mma.sync.aligned.m16n8k8.row.col.f32.tf32.tf32.f32 "
        "{%0,%1,%2,%3}, {%4,%5,%6,%7}, {%8,%9}, {%0,%1,%2,%3};"
        : "+f"(c[0]), "+f"(c[1]), "+f"(c[2]), "+f"(c[3])
        : "r"(a[0]), "r"(a[1]), "r"(a[2]), "r"(a[3]), "r"(b[0]), "r"(b[1]));
}

__device__ __forceinline__ void ldsm4(unsigned* r, uint32_t addr) {
    asm volatile("ldmatrix.sync.aligned.m8n8.x4.shared.b16 {%0,%1,%2,%3}, [%4];"
        : "=r"(r[0]), "=r"(r[1]), "=r"(r[2]), "=r"(r[3]) : "r"(addr));
}

#define CPA(dst, src) \
    asm volatile("cp.async.cg.shared.global [%0], [%1], 16;" :: "r"(dst), "l"(src))
#define CPC() asm volatile("cp.async.commit_group;" ::: "memory")
#define CPW(n) asm volatile("cp.async.wait_group %0;" :: "n"(n) : "memory")

// ---------------------------------------------------------------------------
// prep: RNA-round fp32 -> tf32 bits, elementwise (float4 granularity)
// ---------------------------------------------------------------------------
__global__ __launch_bounds__(256)
void prep_round(const float* __restrict__ src, float* __restrict__ dst, int n4)
{
    const int i = blockIdx.x * 256 + threadIdx.x;
    if (i < n4) {
        float4 v = ((const float4*)src)[i];
        v.x = rtf(v.x); v.y = rtf(v.y); v.z = rtf(v.z); v.w = rtf(v.w);
        ((float4*)dst)[i] = v;
    }
}

// ---------------------------------------------------------------------------
// Projection GEMM: C[4096,512] = A[4096,512] @ W[512,512]^T, (acc+bias)*scale
// MODE: 0 = flat [B,S,D] (final, fp32), 1 = split heads (tf32-rounded),
//       2 = V transposed [B,H,d,S] (tf32-rounded)
// 128x64 block tile, 8 warps (4x2), warp tile 32x32, K-chunk 32,
// cp.async double-buffered. Inputs must already be tf32-rounded.
// ---------------------------------------------------------------------------
#define PBM 128
#define PBN 64
#define PBK 32
#define PLD 36       // 36 % 32 == 4 -> conflict-free ldmatrix rows
#define TLD 132      // transpose stage leading dim
#define PBUFW (PBM*PLD + PBN*PLD)          // words per buffer (6912)
#define PROJ_SMEM (2 * PBUFW * 4)          // 55296 B

template<int MODE>
__global__ __launch_bounds__(256)
void proj_mma(const float* __restrict__ A, const float* __restrict__ W,
              const float* __restrict__ bias, float* __restrict__ out,
              float scale)
{
    extern __shared__ unsigned psm[];

    const int tid  = threadIdx.x;
    const int lane = tid & 31;
    const int wid  = tid >> 5;
    const int wr   = wid >> 1;      // 0..3
    const int wc   = wid & 1;       // 0..1
    const int g    = lane >> 2;     // 0..7
    const int t4   = lane & 3;      // 0..3
    const int bm   = blockIdx.y;
    const int bn   = blockIdx.x;

    const float* Ag = A + (size_t)bm * PBM * DM;
    const float* Wg = W + (size_t)bn * PBN * DM;

    const uint32_t sb   = (uint32_t)__cvta_generic_to_shared(psm);
    const uint32_t BUFB = PBUFW * 4;          // bytes per buffer
    const uint32_t bOff = PBM * PLD * 4;      // B region offset within buffer

    const int lr7 = lane & 7, lb3 = (lane >> 3) & 1, lb4 = (lane >> 4) & 1;
    uint32_t aAddr[2], bAddr[2];
#pragma unroll
    for (int i = 0; i < 2; i++)
        aAddr[i] = sb + ((wr*32 + i*16 + lr7 + lb3*8) * PLD + lb4*4) * 4;
#pragma unroll
    for (int jj = 0; jj < 2; jj++)
        bAddr[jj] = sb + bOff + ((wc*32 + jj*16 + lr7 + lb4*8) * PLD + lb3*4) * 4;

    const int cr = tid >> 3, cq = tid & 7;    // copy row / quad

    // prologue: chunk 0 -> buf 0
#pragma unroll
    for (int i = 0; i < 4; i++) {
        const int r = cr + i * 32;
        CPA(sb + (r*PLD + cq*4)*4, Ag + (size_t)r * DM + cq*4);
    }
#pragma unroll
    for (int i = 0; i < 2; i++) {
        const int r = cr + i * 32;
        CPA(sb + bOff + (r*PLD + cq*4)*4, Wg + (size_t)r * DM + cq*4);
    }
    CPC();

    float acc[2][4][4];
#pragma unroll
    for (int i = 0; i < 2; i++)
#pragma unroll
        for (int j = 0; j < 4; j++)
#pragma unroll
            for (int r = 0; r < 4; r++) acc[i][j][r] = 0.f;

    for (int c = 0; c < DM / PBK; c++) {
        const uint32_t cu = (c & 1) * BUFB;
        if (c < DM / PBK - 1) {
            __syncthreads();                  // buf (c+1)&1 fully consumed
            const uint32_t nb = ((c + 1) & 1) * BUFB;
            const int k0 = (c + 1) * PBK;
#pragma unroll
            for (int i = 0; i < 4; i++) {
                const int r = cr + i * 32;
                CPA(sb + nb + (r*PLD + cq*4)*4, Ag + (size_t)r * DM + k0 + cq*4);
            }
#pragma unroll
            for (int i = 0; i < 2; i++) {
                const int r = cr + i * 32;
                CPA(sb + nb + bOff + (r*PLD + cq*4)*4, Wg + (size_t)r * DM + k0 + cq*4);
            }
            CPC();
            CPW(1);
        } else {
            CPW(0);
        }
        __syncthreads();

#pragma unroll
        for (int kk = 0; kk < PBK / 8; kk++) {
            unsigned af[2][4], bf[2][4];
            ldsm4(af[0], aAddr[0] + cu + kk * 32);
            ldsm4(af[1], aAddr[1] + cu + kk * 32);
            ldsm4(bf[0], bAddr[0] + cu + kk * 32);
            ldsm4(bf[1], bAddr[1] + cu + kk * 32);
#pragma unroll
            for (int i = 0; i < 2; i++) {
                mma8(acc[i][0], af[i], bf[0]);
                mma8(acc[i][1], af[i], bf[0] + 2);
                mma8(acc[i][2], af[i], bf[1]);
                mma8(acc[i][3], af[i], bf[1] + 2);
            }
        }
    }

    if (MODE == 2) {
        // stage (bias-added, tf32-rounded) tile transposed in smem
        float* Ts = (float*)psm;
        __syncthreads();
#pragma unroll
        for (int i = 0; i < 2; i++) {
            const int ss = wr*32 + i*16 + g;
#pragma unroll
            for (int j = 0; j < 4; j++) {
                const int cc = wc*32 + j*8 + 2*t4;
                const float b0 = bias[bn*PBN + cc], b1 = bias[bn*PBN + cc + 1];
                Ts[cc * TLD + ss]           = rtf(acc[i][j][0] + b0);
                Ts[(cc + 1) * TLD + ss]     = rtf(acc[i][j][1] + b1);
                Ts[cc * TLD + ss + 8]       = rtf(acc[i][j][2] + b0);
                Ts[(cc + 1) * TLD + ss + 8] = rtf(acc[i][j][3] + b1);
            }
        }
        __syncthreads();
        const int bb = bm >> 4;
        const int sbase = (bm & 15) * 128;
        float* vout = out + (((size_t)bb * NH + bn) * DH) * SEQ;
#pragma unroll
        for (int t = 0; t < 8; t++) {
            const int idx = tid + t * 256;     // 2048 float4 slots
            const int cc = idx >> 5;
            const int sl = (idx & 31) * 4;
            float4 val = *(float4*)&Ts[cc * TLD + sl];
            *(float4*)(vout + (size_t)cc * SEQ + sbase + sl) = val;
        }
        return;
    }

#pragma unroll
    for (int i = 0; i < 2; i++) {
        const int row0 = bm * PBM + wr * 32 + i * 16 + g;
        const int row1 = row0 + 8;
#pragma unroll
        for (int j = 0; j < 4; j++) {
            const int col0 = bn * PBN + wc * 32 + j * 8 + 2 * t4;
            float v00 = (acc[i][j][0] + bias[col0])     * scale;
            float v01 = (acc[i][j][1] + bias[col0 + 1]) * scale;
            float v10 = (acc[i][j][2] + bias[col0])     * scale;
            float v11 = (acc[i][j][3] + bias[col0 + 1]) * scale;
            if (MODE == 1) {
                v00 = rtf(v00); v01 = rtf(v01); v10 = rtf(v10); v11 = rtf(v11);
                const int b0 = row0 >> 11, s0 = row0 & (SEQ - 1);
                const int b1 = row1 >> 11, s1 = row1 & (SEQ - 1);
                const int hh = col0 >> 6,  cc = col0 & (DH - 1);
                float* p0 = &out[(((size_t)b0 * NH + hh) * SEQ + s0) * DH + cc];
                p0[0] = v00; p0[1] = v01;
                float* p1 = &out[(((size_t)b1 * NH + hh) * SEQ + s1) * DH + cc];
                p1[0] = v10; p1[1] = v11;
            } else {
                float* p0 = &out[(size_t)row0 * DM + col0];
                p0[0] = v00; p0[1] = v01;
                float* p1 = &out[(size_t)row1 * DM + col0];
                p1[0] = v10; p1[1] = v11;
            }
        }
    }
}

// ---------------------------------------------------------------------------
// Flash attention, tf32 mma + ldmatrix + cp.async double-buffered K/V.
// Br=128, Bc=64. 8 warps x 16 rows (in-register softmax).
// Q fragments live in registers. Inputs already tf32-rounded.
// smem: KV bufs 2 x (K 64xALD + V 64xALD) + Ps 128xALD = 104448 B
// ---------------------------------------------------------------------------
#define ALD 68
#define KVSTRIDE (2 * 64 * ALD * 4)                  // bytes per KV buffer
#define ATT_SMEM_BYTES (2 * KVSTRIDE + 128 * ALD * 4) // 104448

__global__ __launch_bounds__(256, 2)
void attn_mma(const float* __restrict__ Q, const float* __restrict__ K,
              const float* __restrict__ VT, float* __restrict__ out)
{
    extern __shared__ unsigned sm[];

    const int tid  = threadIdx.x;
    const int lane = tid & 31;
    const int wid  = tid >> 5;
    const int wrow = wid * 16;
    const int g    = lane >> 2;
    const int t4   = lane & 3;
    const int qt   = blockIdx.x;
    const int h    = blockIdx.y;
    const int b    = blockIdx.z;

    const float* Qg = Q  + (((size_t)b * NH + h) * SEQ + qt * 128) * DH;
    const float* Kg = K  + ((size_t)b * NH + h) * SEQ * DH;
    const float* Vg = VT + ((size_t)b * NH + h) * DH * SEQ;   // [dh][tok]

    const uint32_t sb  = (uint32_t)__cvta_generic_to_shared(sm);
    const uint32_t psB = sb + 2 * KVSTRIDE;   // Ps (and Q staging) base

    const int lr7 = lane & 7, lb3 = (lane >> 3) & 1, lb4 = (lane >> 4) & 1;
    const uint32_t bK0 = sb + ((lr7 + lb4 * 8) * ALD + lb3 * 4) * 4;
    const uint32_t bV0 = bK0 + 64 * ALD * 4;
    const uint32_t aP0 = psB + ((wrow + lr7 + lb3 * 8) * ALD + lb4 * 4) * 4;

    const int r16 = tid >> 4, q16 = tid & 15;

    // ---- prologue: stage Q into Ps region + K0/V0 into buf0, via cp.async
#pragma unroll
    for (int i = 0; i < 8; i++) {
        const int rr = r16 + i * 16;
        CPA(psB + (rr * ALD + q16 * 4) * 4, Qg + rr * DH + q16 * 4);
    }
    CPC();
#pragma unroll
    for (int i = 0; i < 4; i++) {
        const int rr = r16 + i * 16;
        CPA(sb + (rr * ALD + q16 * 4) * 4, Kg + rr * DH + q16 * 4);
        CPA(sb + 64 * ALD * 4 + (rr * ALD + q16 * 4) * 4,
            Vg + (size_t)rr * SEQ + q16 * 4);
    }
    CPC();
    CPW(1);                 // Q group complete
    __syncthreads();

    // Q fragments -> registers (warp-local rows of the staging region)
    unsigned Qf[8][4];
#pragma unroll
    for (int kk = 0; kk < 8; kk++) ldsm4(Qf[kk], aP0 + kk * 32);

    float o[8][4];
#pragma unroll
    for (int j = 0; j < 8; j++)
#pragma unroll
        for (int r = 0; r < 4; r++) o[j][r] = 0.f;
    float mA = -1e30f, mB = -1e30f, lA = 0.f, lB = 0.f;

    for (int kt = 0; kt < SEQ / 64; kt++) {
        const uint32_t cu = (uint32_t)(kt & 1) * KVSTRIDE;
        if (kt < SEQ / 64 - 1) {
            __syncthreads();    // alternate buffer fully consumed by all warps
            const uint32_t nb = (uint32_t)((kt + 1) & 1) * KVSTRIDE;
            const float* Kt = Kg + (size_t)(kt + 1) * 64 * DH;
            const float* Vt = Vg + (kt + 1) * 64;
#pragma unroll
            for (int i = 0; i < 4; i++) {
                const int rr = r16 + i * 16;
                CPA(sb + nb + (rr * ALD + q16 * 4) * 4, Kt + rr * DH + q16 * 4);
                CPA(sb + nb + 64 * ALD * 4 + (rr * ALD + q16 * 4) * 4,
                    Vt + (size_t)rr * SEQ + q16 * 4);
            }
            CPC();
            CPW(1);             // current buffer's group complete
        } else {
            CPW(0);
        }
        __syncthreads();

        // ---- S = Q @ K^T (warp: 16 rows x 64 cols)
        float s[8][4];
#pragma unroll
        for (int j = 0; j < 8; j++)
#pragma unroll
            for (int r = 0; r < 4; r++) s[j][r] = 0.f;
#pragma unroll
        for (int kk = 0; kk < 8; kk++) {
#pragma unroll
            for (int jj = 0; jj < 4; jj++) {
                unsigned bk[4];
                ldsm4(bk, bK0 + cu + jj * (16 * ALD * 4) + kk * 32);
                mma8(s[2 * jj],     Qf[kk], bk);
                mma8(s[2 * jj + 1], Qf[kk], bk + 2);
            }
        }

        // ---- in-register online softmax (rows g / g+8, quad shfl)
        float mxA = -1e30f, mxB = -1e30f;
#pragma unroll
        for (int j = 0; j < 8; j++) {
            mxA = fmaxf(mxA, fmaxf(s[j][0], s[j][1]));
            mxB = fmaxf(mxB, fmaxf(s[j][2], s[j][3]));
        }
        mxA = fmaxf(mxA, __shfl_xor_sync(0xffffffffu, mxA, 1));
        mxA = fmaxf(mxA, __shfl_xor_sync(0xffffffffu, mxA, 2));
        mxB = fmaxf(mxB, __shfl_xor_sync(0xffffffffu, mxB, 1));
        mxB = fmaxf(mxB, __shfl_xor_sync(0xffffffffu, mxB, 2));
        const float mnA = fmaxf(mA, mxA), mnB = fmaxf(mB, mxB);
        const float alA = __expf(mA - mnA), alB = __expf(mB - mnB);
        float suA = 0.f, suB = 0.f;
#pragma unroll
        for (int j = 0; j < 8; j++) {
            s[j][0] = __expf(s[j][0] - mnA);
            s[j][1] = __expf(s[j][1] - mnA);
            s[j][2] = __expf(s[j][2] - mnB);
            s[j][3] = __expf(s[j][3] - mnB);
            suA += s[j][0] + s[j][1];
            suB += s[j][2] + s[j][3];
        }
        suA += __shfl_xor_sync(0xffffffffu, suA, 1);
        suA += __shfl_xor_sync(0xffffffffu, suA, 2);
        suB += __shfl_xor_sync(0xffffffffu, suB, 1);
        suB += __shfl_xor_sync(0xffffffffu, suB, 2);
        lA = lA * alA + suA;  mA = mnA;
        lB = lB * alB + suB;  mB = mnB;

        // rescale O
#pragma unroll
        for (int j = 0; j < 8; j++) {
            o[j][0] *= alA; o[j][1] *= alA;
            o[j][2] *= alB; o[j][3] *= alB;
        }

        // ---- write P (RNA-rounded tf32 bits), read back as A-frags
        unsigned* Ps = sm + 2 * (KVSTRIDE / 4);
        __syncwarp();
#pragma unroll
        for (int j = 0; j < 8; j++) {
            uint2 u0, u1;
            u0.x = f2tf(s[j][0]); u0.y = f2tf(s[j][1]);
            u1.x = f2tf(s[j][2]); u1.y = f2tf(s[j][3]);
            *(uint2*)&Ps[(wrow + g)     * ALD + j * 8 + 2 * t4] = u0;
            *(uint2*)&Ps[(wrow + g + 8) * ALD + j * 8 + 2 * t4] = u1;
        }
        __syncwarp();

        // ---- O += P @ V
#pragma unroll
        for (int kc = 0; kc < 8; kc++) {
            unsigned ap[4];
            ldsm4(ap, aP0 + kc * 32);
#pragma unroll
            for (int jj = 0; jj < 4; jj++) {
                unsigned bv[4];
                ldsm4(bv, bV0 + cu + jj * (16 * ALD * 4) + kc * 32);
                mma8(o[2 * jj],     ap, bv);
                mma8(o[2 * jj + 1], ap, bv + 2);
            }
        }
    }

    // ---- epilogue (tf32-rounded so the O-projection's loads are exact)
    const float invA = 1.f / lA, invB = 1.f / lB;
    const int rA = qt * 128 + wrow + g;
    float* oA = out + ((size_t)(b * SEQ + rA)) * DM + h * DH;
    float* oB = oA + (size_t)8 * DM;
#pragma unroll
    for (int j = 0; j < 8; j++) {
        const int col = j * 8 + 2 * t4;
        float2 vA, vB;
        vA.x = rtf(o[j][0] * invA); vA.y = rtf(o[j][1] * invA);
        vB.x = rtf(o[j][2] * invB); vB.y = rtf(o[j][3] * invB);
        *(float2*)(oA + col) = vA;
        *(float2*)(oB + col) = vB;
    }
}

// ---------------------------------------------------------------------------
extern "C" void kernel_launch(void* const* d_in, const int* in_sizes, int n_in,
                              void* d_out, int out_size)
{
    const float* x  = (const float*)d_in[0];
    const float* Wq = (const float*)d_in[1];
    const float* bq = (const float*)d_in[2];
    const float* Wk = (const float*)d_in[3];
    const float* bk = (const float*)d_in[4];
    const float* Wv = (const float*)d_in[5];
    const float* bv = (const float*)d_in[6];
    const float* Wo = (const float*)d_in[7];
    const float* bo = (const float*)d_in[8];
    float* out = (float*)d_out;

    float *xr, *wr_, *q, *k, *vt, *att;
    cudaGetSymbolAddress((void**)&xr,  g_x);
    cudaGetSymbolAddress((void**)&wr_, g_w);
    cudaGetSymbolAddress((void**)&q,   g_q);
    cudaGetSymbolAddress((void**)&k,   g_k);
    cudaGetSymbolAddress((void**)&vt,  g_vt);
    cudaGetSymbolAddress((void**)&att, g_att);

    cudaFuncSetAttribute(proj_mma<0>,
        cudaFuncAttributeMaxDynamicSharedMemorySize, PROJ_SMEM);
    cudaFuncSetAttribute(proj_mma<1>,
        cudaFuncAttributeMaxDynamicSharedMemorySize, PROJ_SMEM);
    cudaFuncSetAttribute(proj_mma<2>,
        cudaFuncAttributeMaxDynamicSharedMemorySize, PROJ_SMEM);
    cudaFuncSetAttribute(attn_mma,
        cudaFuncAttributeMaxDynamicSharedMemorySize, ATT_SMEM_BYTES);

    // RNA-round all GEMM inputs to tf32 once
    const int XN4 = NTOK * DM / 4;      // 524288
    const int WN4 = DM * DM / 4;        // 65536
    prep_round<<<XN4 / 256, 256>>>(x,  xr,             XN4);
    prep_round<<<WN4 / 256, 256>>>(Wq, wr_ + 0*DM*DM,  WN4);
    prep_round<<<WN4 / 256, 256>>>(Wk, wr_ + 1*DM*DM,  WN4);
    prep_round<<<WN4 / 256, 256>>>(Wv, wr_ + 2*DM*DM,  WN4);
    prep_round<<<WN4 / 256, 256>>>(Wo, wr_ + 3*DM*DM,  WN4);

    const dim3 pgrid(DM / PBN, NTOK / PBM);   // (8, 32)
    const float qscale = 1.0f / 8.0f;         // 1/sqrt(DH)

    proj_mma<1><<<pgrid, 256, PROJ_SMEM>>>(xr, wr_ + 0*DM*DM, bq, q,  qscale);
    proj_mma<1><<<pgrid, 256, PROJ_SMEM>>>(xr, wr_ + 1*DM*DM, bk, k,  1.0f);
    proj_mma<2><<<pgrid, 256, PROJ_SMEM>>>(xr, wr_ + 2*DM*DM, bv, vt, 1.0f);

    attn_mma<<<dim3(SEQ / 128, NH, BAT), 256, ATT_SMEM_BYTES>>>(q, k, vt, att);

    proj_mma<0><<<pgrid, 256, PROJ_SMEM>>>(att, wr_ + 3*DM*DM, bo, out, 1.0f);
}

// round 6
// speedup vs baseline: 4.7627x; 1.0312x over previous
#include <cuda_runtime.h>
#include <math.h>
#include <stdint.h>

#define DM   512
#define NH   8
#define DH   64
#define BAT  2
#define SEQ  2048
#define NTOK (BAT*SEQ)   // 4096

// Scratch (device globals)
__device__ float g_x[NTOK*DM];           // x pre-rounded to tf32
__device__ float g_w[4*DM*DM];           // Wq,Wk,Wv,Wo pre-rounded to tf32
__device__ float g_q[BAT*NH*SEQ*DH];     // [B,H,S,d], pre-scaled by 1/8, tf32
__device__ float g_k[BAT*NH*SEQ*DH];     // [B,H,S,d], tf32
__device__ float g_vt[BAT*NH*DH*SEQ];    // V TRANSPOSED [B,H,d,S], tf32
__device__ float g_att[NTOK*DM];         // attention output [B,S,D], tf32

// ---------------------------------------------------------------------------
// helpers
// ---------------------------------------------------------------------------
__device__ __forceinline__ unsigned f2tf(float f) {
    unsigned u;
    asm("cvt.rna.tf32.f32 %0, %1;" : "=r"(u) : "f"(f));
    return u;
}
__device__ __forceinline__ float rtf(float f) { return __uint_as_float(f2tf(f)); }

__device__ __forceinline__ void mma8(float* c, const unsigned* a, const unsigned* b) {
    asm volatile(
        "mma.sync.aligned.m16n8k8.row.col.f32.tf32.tf32.f32 "
        "{%0,%1,%2,%3}, {%4,%5,%6,%7}, {%8,%9}, {%0,%1,%2,%3};"
        : "+f"(c[0]), "+f"(c[1]), "+f"(c[2]), "+f"(c[3])
        : "r"(a[0]), "r"(a[1]), "r"(a[2]), "r"(a[3]), "r"(b[0]), "r"(b[1]));
}

__device__ __forceinline__ void ldsm4(unsigned* r, uint32_t addr) {
    asm volatile("ldmatrix.sync.aligned.m8n8.x4.shared.b16 {%0,%1,%2,%3}, [%4];"
        : "=r"(r[0]), "=r"(r[1]), "=r"(r[2]), "=r"(r[3]) : "r"(addr));
}

#define CPA(dst, src) \
    asm volatile("cp.async.cg.shared.global [%0], [%1], 16;" :: "r"(dst), "l"(src))
#define CPC() asm volatile("cp.async.commit_group;" ::: "memory")
#define CPW(n) asm volatile("cp.async.wait_group %0;" :: "n"(n) : "memory")

// ---------------------------------------------------------------------------
// prep: RNA-round fp32 -> tf32, elementwise
// ---------------------------------------------------------------------------
__global__ __launch_bounds__(256)
void prep_x(const float* __restrict__ src, float* __restrict__ dst, int n4)
{
    const int i = blockIdx.x * 256 + threadIdx.x;
    if (i < n4) {
        float4 v = ((const float4*)src)[i];
        v.x = rtf(v.x); v.y = rtf(v.y); v.z = rtf(v.z); v.w = rtf(v.w);
        ((float4*)dst)[i] = v;
    }
}

__global__ __launch_bounds__(256)
void prep_w4(const float* __restrict__ w0, const float* __restrict__ w1,
             const float* __restrict__ w2, const float* __restrict__ w3,
             float* __restrict__ dst, int n4)
{
    const int y = blockIdx.y;
    const float* src = (y == 0) ? w0 : (y == 1) ? w1 : (y == 2) ? w2 : w3;
    const int i = blockIdx.x * 256 + threadIdx.x;
    if (i < n4) {
        float4 v = ((const float4*)src)[i];
        v.x = rtf(v.x); v.y = rtf(v.y); v.z = rtf(v.z); v.w = rtf(v.w);
        ((float4*)(dst + (size_t)y * DM * DM))[i] = v;
    }
}

// ---------------------------------------------------------------------------
// Projection GEMM: C[4096,512] = A[4096,512] @ W[512,512]^T, (acc+bias)*scale
// MODE: 0 = flat [B,S,D] (final, fp32), 1 = split heads (tf32-rounded),
//       2 = V transposed [B,H,d,S] (tf32-rounded)
// CTA tile 128x128, 8 warps (4 row x 2 col), warp tile 32x64, K-chunk 32,
// cp.async double-buffered. Inputs must already be tf32-rounded.
// ---------------------------------------------------------------------------
#define PBM 128
#define PBN 128
#define PBK 32
#define PLD 36       // 36 % 32 == 4 -> conflict-free ldmatrix rows
#define TLD 132      // transpose stage leading dim
#define PBUFW ((PBM + PBN) * PLD)          // words per buffer (9216)
#define PROJ_SMEM (2 * PBUFW * 4)          // 73728 B

template<int MODE>
__global__ __launch_bounds__(256)
void proj_mma(const float* __restrict__ A, const float* __restrict__ W,
              const float* __restrict__ bias, float* __restrict__ out,
              float scale)
{
    extern __shared__ unsigned psm[];

    const int tid  = threadIdx.x;
    const int lane = tid & 31;
    const int wid  = tid >> 5;
    const int wr   = wid >> 1;      // 0..3  (32-row slices)
    const int wc   = wid & 1;       // 0..1  (64-col slices)
    const int g    = lane >> 2;     // 0..7
    const int t4   = lane & 3;      // 0..3
    const int bm   = blockIdx.y;
    const int bn   = blockIdx.x;

    const float* Ag = A + (size_t)bm * PBM * DM;
    const float* Wg = W + (size_t)bn * PBN * DM;

    const uint32_t sb   = (uint32_t)__cvta_generic_to_shared(psm);
    const uint32_t BUFB = PBUFW * 4;          // bytes per buffer
    const uint32_t bOff = PBM * PLD * 4;      // B region offset within buffer

    const int lr7 = lane & 7, lb3 = (lane >> 3) & 1, lb4 = (lane >> 4) & 1;
    uint32_t aAddr[2], bAddr[4];
#pragma unroll
    for (int i = 0; i < 2; i++)
        aAddr[i] = sb + ((wr*32 + i*16 + lr7 + lb3*8) * PLD + lb4*4) * 4;
#pragma unroll
    for (int jj = 0; jj < 4; jj++)
        bAddr[jj] = sb + bOff + ((wc*64 + jj*16 + lr7 + lb4*8) * PLD + lb3*4) * 4;

    const int cr = tid >> 3, cq = tid & 7;    // copy row (0..31) / quad

    // prologue: chunk 0 -> buf 0
#pragma unroll
    for (int i = 0; i < 4; i++) {
        const int r = cr + i * 32;
        CPA(sb + (r*PLD + cq*4)*4, Ag + (size_t)r * DM + cq*4);
    }
#pragma unroll
    for (int i = 0; i < 4; i++) {
        const int r = cr + i * 32;
        CPA(sb + bOff + (r*PLD + cq*4)*4, Wg + (size_t)r * DM + cq*4);
    }
    CPC();

    float acc[2][8][4];
#pragma unroll
    for (int i = 0; i < 2; i++)
#pragma unroll
        for (int j = 0; j < 8; j++)
#pragma unroll
            for (int r = 0; r < 4; r++) acc[i][j][r] = 0.f;

    for (int c = 0; c < DM / PBK; c++) {
        const uint32_t cu = (c & 1) * BUFB;
        if (c < DM / PBK - 1) {
            __syncthreads();                  // buf (c+1)&1 fully consumed
            const uint32_t nb = ((c + 1) & 1) * BUFB;
            const int k0 = (c + 1) * PBK;
#pragma unroll
            for (int i = 0; i < 4; i++) {
                const int r = cr + i * 32;
                CPA(sb + nb + (r*PLD + cq*4)*4, Ag + (size_t)r * DM + k0 + cq*4);
            }
#pragma unroll
            for (int i = 0; i < 4; i++) {
                const int r = cr + i * 32;
                CPA(sb + nb + bOff + (r*PLD + cq*4)*4, Wg + (size_t)r * DM + k0 + cq*4);
            }
            CPC();
            CPW(1);
        } else {
            CPW(0);
        }
        __syncthreads();

#pragma unroll
        for (int kk = 0; kk < PBK / 8; kk++) {
            unsigned af[2][4], bf[4][4];
            ldsm4(af[0], aAddr[0] + cu + kk * 32);
            ldsm4(af[1], aAddr[1] + cu + kk * 32);
#pragma unroll
            for (int jj = 0; jj < 4; jj++)
                ldsm4(bf[jj], bAddr[jj] + cu + kk * 32);
#pragma unroll
            for (int i = 0; i < 2; i++)
#pragma unroll
                for (int j = 0; j < 8; j++)
                    mma8(acc[i][j], af[i], bf[j >> 1] + (j & 1) * 2);
        }
    }

    if (MODE == 2) {
        // stage (bias-added, tf32-rounded) tile transposed in smem
        float* Ts = (float*)psm;              // 128 cols x TLD
        __syncthreads();
#pragma unroll
        for (int i = 0; i < 2; i++) {
            const int ss = wr*32 + i*16 + g;
#pragma unroll
            for (int j = 0; j < 8; j++) {
                const int cc = wc*64 + j*8 + 2*t4;
                const float b0 = bias[bn*PBN + cc], b1 = bias[bn*PBN + cc + 1];
                Ts[cc * TLD + ss]           = rtf(acc[i][j][0] + b0);
                Ts[(cc + 1) * TLD + ss]     = rtf(acc[i][j][1] + b1);
                Ts[cc * TLD + ss + 8]       = rtf(acc[i][j][2] + b0);
                Ts[(cc + 1) * TLD + ss + 8] = rtf(acc[i][j][3] + b1);
            }
        }
        __syncthreads();
        const int bb = bm >> 4;
        const int sbase = (bm & 15) * 128;
#pragma unroll
        for (int t = 0; t < 16; t++) {
            const int idx = tid + t * 256;     // 4096 float4 slots
            const int cc = idx >> 5;           // 0..127 model-col in block
            const int sl = (idx & 31) * 4;     // 0..124 seq within tile
            const int mc = bn * PBN + cc;
            const int hh = mc >> 6, dd = mc & (DH - 1);
            float4 val = *(float4*)&Ts[cc * TLD + sl];
            *(float4*)(out + (((size_t)bb * NH + hh) * DH + dd) * SEQ + sbase + sl) = val;
        }
        return;
    }

#pragma unroll
    for (int i = 0; i < 2; i++) {
        const int row0 = bm * PBM + wr * 32 + i * 16 + g;
        const int row1 = row0 + 8;
#pragma unroll
        for (int j = 0; j < 8; j++) {
            const int col0 = bn * PBN + wc * 64 + j * 8 + 2 * t4;
            float v00 = (acc[i][j][0] + bias[col0])     * scale;
            float v01 = (acc[i][j][1] + bias[col0 + 1]) * scale;
            float v10 = (acc[i][j][2] + bias[col0])     * scale;
            float v11 = (acc[i][j][3] + bias[col0 + 1]) * scale;
            if (MODE == 1) {
                v00 = rtf(v00); v01 = rtf(v01); v10 = rtf(v10); v11 = rtf(v11);
                const int b0 = row0 >> 11, s0 = row0 & (SEQ - 1);
                const int b1 = row1 >> 11, s1 = row1 & (SEQ - 1);
                const int hh = col0 >> 6,  cc = col0 & (DH - 1);
                float* p0 = &out[(((size_t)b0 * NH + hh) * SEQ + s0) * DH + cc];
                p0[0] = v00; p0[1] = v01;
                float* p1 = &out[(((size_t)b1 * NH + hh) * SEQ + s1) * DH + cc];
                p1[0] = v10; p1[1] = v11;
            } else {
                float* p0 = &out[(size_t)row0 * DM + col0];
                p0[0] = v00; p0[1] = v01;
                float* p1 = &out[(size_t)row1 * DM + col0];
                p1[0] = v10; p1[1] = v11;
            }
        }
    }
}

// ---------------------------------------------------------------------------
// Flash attention, tf32 mma + ldmatrix + cp.async double-buffered K/V.
// Br=128, Bc=64. 8 warps x 16 rows (in-register softmax).
// Q fragments live in registers. Inputs already tf32-rounded.
// smem: KV bufs 2 x (K 64xALD + V 64xALD) + Ps 128xALD = 104448 B
// ---------------------------------------------------------------------------
#define ALD 68
#define KVSTRIDE (2 * 64 * ALD * 4)                  // bytes per KV buffer
#define ATT_SMEM_BYTES (2 * KVSTRIDE + 128 * ALD * 4) // 104448

__global__ __launch_bounds__(256, 2)
void attn_mma(const float* __restrict__ Q, const float* __restrict__ K,
              const float* __restrict__ VT, float* __restrict__ out)
{
    extern __shared__ unsigned sm[];

    const int tid  = threadIdx.x;
    const int lane = tid & 31;
    const int wid  = tid >> 5;
    const int wrow = wid * 16;
    const int g    = lane >> 2;
    const int t4   = lane & 3;
    const int qt   = blockIdx.x;
    const int h    = blockIdx.y;
    const int b    = blockIdx.z;

    const float* Qg = Q  + (((size_t)b * NH + h) * SEQ + qt * 128) * DH;
    const float* Kg = K  + ((size_t)b * NH + h) * SEQ * DH;
    const float* Vg = VT + ((size_t)b * NH + h) * DH * SEQ;   // [dh][tok]

    const uint32_t sb  = (uint32_t)__cvta_generic_to_shared(sm);
    const uint32_t psB = sb + 2 * KVSTRIDE;   // Ps (and Q staging) base

    const int lr7 = lane & 7, lb3 = (lane >> 3) & 1, lb4 = (lane >> 4) & 1;
    const uint32_t bK0 = sb + ((lr7 + lb4 * 8) * ALD + lb3 * 4) * 4;
    const uint32_t bV0 = bK0 + 64 * ALD * 4;
    const uint32_t aP0 = psB + ((wrow + lr7 + lb3 * 8) * ALD + lb4 * 4) * 4;

    const int r16 = tid >> 4, q16 = tid & 15;

    // ---- prologue: stage Q into Ps region + K0/V0 into buf0, via cp.async
#pragma unroll
    for (int i = 0; i < 8; i++) {
        const int rr = r16 + i * 16;
        CPA(psB + (rr * ALD + q16 * 4) * 4, Qg + rr * DH + q16 * 4);
    }
    CPC();
#pragma unroll
    for (int i = 0; i < 4; i++) {
        const int rr = r16 + i * 16;
        CPA(sb + (rr * ALD + q16 * 4) * 4, Kg + rr * DH + q16 * 4);
        CPA(sb + 64 * ALD * 4 + (rr * ALD + q16 * 4) * 4,
            Vg + (size_t)rr * SEQ + q16 * 4);
    }
    CPC();
    CPW(1);                 // Q group complete
    __syncthreads();

    // Q fragments -> registers (warp-local rows of the staging region)
    unsigned Qf[8][4];
#pragma unroll
    for (int kk = 0; kk < 8; kk++) ldsm4(Qf[kk], aP0 + kk * 32);

    float o[8][4];
#pragma unroll
    for (int j = 0; j < 8; j++)
#pragma unroll
        for (int r = 0; r < 4; r++) o[j][r] = 0.f;
    float mA = -1e30f, mB = -1e30f, lA = 0.f, lB = 0.f;

    for (int kt = 0; kt < SEQ / 64; kt++) {
        const uint32_t cu = (uint32_t)(kt & 1) * KVSTRIDE;
        if (kt < SEQ / 64 - 1) {
            __syncthreads();    // alternate buffer fully consumed by all warps
            const uint32_t nb = (uint32_t)((kt + 1) & 1) * KVSTRIDE;
            const float* Kt = Kg + (size_t)(kt + 1) * 64 * DH;
            const float* Vt = Vg + (kt + 1) * 64;
#pragma unroll
            for (int i = 0; i < 4; i++) {
                const int rr = r16 + i * 16;
                CPA(sb + nb + (rr * ALD + q16 * 4) * 4, Kt + rr * DH + q16 * 4);
                CPA(sb + nb + 64 * ALD * 4 + (rr * ALD + q16 * 4) * 4,
                    Vt + (size_t)rr * SEQ + q16 * 4);
            }
            CPC();
            CPW(1);             // current buffer's group complete
        } else {
            CPW(0);
        }
        __syncthreads();

        // ---- S = Q @ K^T (warp: 16 rows x 64 cols)
        float s[8][4];
#pragma unroll
        for (int j = 0; j < 8; j++)
#pragma unroll
            for (int r = 0; r < 4; r++) s[j][r] = 0.f;
#pragma unroll
        for (int kk = 0; kk < 8; kk++) {
#pragma unroll
            for (int jj = 0; jj < 4; jj++) {
                unsigned bk[4];
                ldsm4(bk, bK0 + cu + jj * (16 * ALD * 4) + kk * 32);
                mma8(s[2 * jj],     Qf[kk], bk);
                mma8(s[2 * jj + 1], Qf[kk], bk + 2);
            }
        }

        // ---- in-register online softmax (rows g / g+8, quad shfl)
        float mxA = -1e30f, mxB = -1e30f;
#pragma unroll
        for (int j = 0; j < 8; j++) {
            mxA = fmaxf(mxA, fmaxf(s[j][0], s[j][1]));
            mxB = fmaxf(mxB, fmaxf(s[j][2], s[j][3]));
        }
        mxA = fmaxf(mxA, __shfl_xor_sync(0xffffffffu, mxA, 1));
        mxA = fmaxf(mxA, __shfl_xor_sync(0xffffffffu, mxA, 2));
        mxB = fmaxf(mxB, __shfl_xor_sync(0xffffffffu, mxB, 1));
        mxB = fmaxf(mxB, __shfl_xor_sync(0xffffffffu, mxB, 2));
        const float mnA = fmaxf(mA, mxA), mnB = fmaxf(mB, mxB);
        const float alA = __expf(mA - mnA), alB = __expf(mB - mnB);
        float suA = 0.f, suB = 0.f;
#pragma unroll
        for (int j = 0; j < 8; j++) {
            s[j][0] = __expf(s[j][0] - mnA);
            s[j][1] = __expf(s[j][1] - mnA);
            s[j][2] = __expf(s[j][2] - mnB);
            s[j][3] = __expf(s[j][3] - mnB);
            suA += s[j][0] + s[j][1];
            suB += s[j][2] + s[j][3];
        }
        suA += __shfl_xor_sync(0xffffffffu, suA, 1);
        suA += __shfl_xor_sync(0xffffffffu, suA, 2);
        suB += __shfl_xor_sync(0xffffffffu, suB, 1);
        suB += __shfl_xor_sync(0xffffffffu, suB, 2);
        lA = lA * alA + suA;  mA = mnA;
        lB = lB * alB + suB;  mB = mnB;

        // rescale O
#pragma unroll
        for (int j = 0; j < 8; j++) {
            o[j][0] *= alA; o[j][1] *= alA;
            o[j][2] *= alB; o[j][3] *= alB;
        }

        // ---- write P (RNA-rounded tf32 bits), read back as A-frags
        unsigned* Ps = sm + 2 * (KVSTRIDE / 4);
        __syncwarp();
#pragma unroll
        for (int j = 0; j < 8; j++) {
            uint2 u0, u1;
            u0.x = f2tf(s[j][0]); u0.y = f2tf(s[j][1]);
            u1.x = f2tf(s[j][2]); u1.y = f2tf(s[j][3]);
            *(uint2*)&Ps[(wrow + g)     * ALD + j * 8 + 2 * t4] = u0;
            *(uint2*)&Ps[(wrow + g + 8) * ALD + j * 8 + 2 * t4] = u1;
        }
        __syncwarp();

        // ---- O += P @ V
#pragma unroll
        for (int kc = 0; kc < 8; kc++) {
            unsigned ap[4];
            ldsm4(ap, aP0 + kc * 32);
#pragma unroll
            for (int jj = 0; jj < 4; jj++) {
                unsigned bv[4];
                ldsm4(bv, bV0 + cu + jj * (16 * ALD * 4) + kc * 32);
                mma8(o[2 * jj],     ap, bv);
                mma8(o[2 * jj + 1], ap, bv + 2);
            }
        }
    }

    // ---- epilogue (tf32-rounded so the O-projection's loads are exact)
    const float invA = 1.f / lA, invB = 1.f / lB;
    const int rA = qt * 128 + wrow + g;
    float* oA = out + ((size_t)(b * SEQ + rA)) * DM + h * DH;
    float* oB = oA + (size_t)8 * DM;
#pragma unroll
    for (int j = 0; j < 8; j++) {
        const int col = j * 8 + 2 * t4;
        float2 vA, vB;
        vA.x = rtf(o[j][0] * invA); vA.y = rtf(o[j][1] * invA);
        vB.x = rtf(o[j][2] * invB); vB.y = rtf(o[j][3] * invB);
        *(float2*)(oA + col) = vA;
        *(float2*)(oB + col) = vB;
    }
}

// ---------------------------------------------------------------------------
extern "C" void kernel_launch(void* const* d_in, const int* in_sizes, int n_in,
                              void* d_out, int out_size)
{
    const float* x  = (const float*)d_in[0];
    const float* Wq = (const float*)d_in[1];
    const float* bq = (const float*)d_in[2];
    const float* Wk = (const float*)d_in[3];
    const float* bk = (const float*)d_in[4];
    const float* Wv = (const float*)d_in[5];
    const float* bv = (const float*)d_in[6];
    const float* Wo = (const float*)d_in[7];
    const float* bo = (const float*)d_in[8];
    float* out = (float*)d_out;

    float *xr, *wr_, *q, *k, *vt, *att;
    cudaGetSymbolAddress((void**)&xr,  g_x);
    cudaGetSymbolAddress((void**)&wr_, g_w);
    cudaGetSymbolAddress((void**)&q,   g_q);
    cudaGetSymbolAddress((void**)&k,   g_k);
    cudaGetSymbolAddress((void**)&vt,  g_vt);
    cudaGetSymbolAddress((void**)&att, g_att);

    cudaFuncSetAttribute(proj_mma<0>,
        cudaFuncAttributeMaxDynamicSharedMemorySize, PROJ_SMEM);
    cudaFuncSetAttribute(proj_mma<1>,
        cudaFuncAttributeMaxDynamicSharedMemorySize, PROJ_SMEM);
    cudaFuncSetAttribute(proj_mma<2>,
        cudaFuncAttributeMaxDynamicSharedMemorySize, PROJ_SMEM);
    cudaFuncSetAttribute(attn_mma,
        cudaFuncAttributeMaxDynamicSharedMemorySize, ATT_SMEM_BYTES);

    // RNA-round all GEMM inputs to tf32 once (2 launches)
    const int XN4 = NTOK * DM / 4;      // 524288
    const int WN4 = DM * DM / 4;        // 65536
    prep_x<<<XN4 / 256, 256>>>(x, xr, XN4);
    prep_w4<<<dim3(WN4 / 256, 4), 256>>>(Wq, Wk, Wv, Wo, wr_, WN4);

    const dim3 pgrid(DM / PBN, NTOK / PBM);   // (4, 32)
    const float qscale = 1.0f / 8.0f;         // 1/sqrt(DH)

    // launches 2,3,4 -> attn is launch index 5 (ncu -s 5 captures it)
    proj_mma<1><<<pgrid, 256, PROJ_SMEM>>>(xr, wr_ + 0*DM*DM, bq, q,  qscale);
    proj_mma<1><<<pgrid, 256, PROJ_SMEM>>>(xr, wr_ + 1*DM*DM, bk, k,  1.0f);
    proj_mma<2><<<pgrid, 256, PROJ_SMEM>>>(xr, wr_ + 2*DM*DM, bv, vt, 1.0f);

    attn_mma<<<dim3(SEQ / 128, NH, BAT), 256, ATT_SMEM_BYTES>>>(q, k, vt, att);

    proj_mma<0><<<pgrid, 256, PROJ_SMEM>>>(att, wr_ + 3*DM*DM, bo, out, 1.0f);
}

// round 7
// speedup vs baseline: 4.9177x; 1.0325x over previous
#include <cuda_runtime.h>
#include <math.h>
#include <stdint.h>

#define DM   512
#define NH   8
#define DH   64
#define BAT  2
#define SEQ  2048
#define NTOK (BAT*SEQ)   // 4096

// Scratch (device globals)
__device__ float g_x[NTOK*DM];           // x pre-rounded to tf32
__device__ float g_w[4*DM*DM];           // Wq,Wk,Wv,Wo pre-rounded to tf32
__device__ float g_q[BAT*NH*SEQ*DH];     // [B,H,S,d], pre-scaled by 1/8, tf32
__device__ float g_k[BAT*NH*SEQ*DH];     // [B,H,S,d], tf32
__device__ float g_vt[BAT*NH*DH*SEQ];    // V TRANSPOSED [B,H,d,S], tf32
__device__ float g_att[NTOK*DM];         // attention output [B,S,D], tf32

// ---------------------------------------------------------------------------
// helpers
// ---------------------------------------------------------------------------
__device__ __forceinline__ unsigned f2tf(float f) {
    unsigned u;
    asm("cvt.rna.tf32.f32 %0, %1;" : "=r"(u) : "f"(f));
    return u;
}
__device__ __forceinline__ float rtf(float f) { return __uint_as_float(f2tf(f)); }

__device__ __forceinline__ void mma8(float* c, const unsigned* a, const unsigned* b) {
    asm volatile(
        "mma.sync.aligned.m16n8k8.row.col.f32.tf32.tf32.f32 "
        "{%0,%1,%2,%3}, {%4,%5,%6,%7}, {%8,%9}, {%0,%1,%2,%3};"
        : "+f"(c[0]), "+f"(c[1]), "+f"(c[2]), "+f"(c[3])
        : "r"(a[0]), "r"(a[1]), "r"(a[2]), "r"(a[3]), "r"(b[0]), "r"(b[1]));
}

__device__ __forceinline__ void ldsm4(unsigned* r, uint32_t addr) {
    asm volatile("ldmatrix.sync.aligned.m8n8.x4.shared.b16 {%0,%1,%2,%3}, [%4];"
        : "=r"(r[0]), "=r"(r[1]), "=r"(r[2]), "=r"(r[3]) : "r"(addr));
}

#define CPA(dst, src) \
    asm volatile("cp.async.cg.shared.global [%0], [%1], 16;" :: "r"(dst), "l"(src))
#define CPC() asm volatile("cp.async.commit_group;" ::: "memory")
#define CPW(n) asm volatile("cp.async.wait_group %0;" :: "n"(n) : "memory")

// ---------------------------------------------------------------------------
// prep: RNA-round fp32 -> tf32, elementwise
// ---------------------------------------------------------------------------
__global__ __launch_bounds__(256)
void prep_x(const float* __restrict__ src, float* __restrict__ dst, int n4)
{
    const int i = blockIdx.x * 256 + threadIdx.x;
    if (i < n4) {
        float4 v = ((const float4*)src)[i];
        v.x = rtf(v.x); v.y = rtf(v.y); v.z = rtf(v.z); v.w = rtf(v.w);
        ((float4*)dst)[i] = v;
    }
}

// ---------------------------------------------------------------------------
// Fused QKV projection: for mat in {Q,K,V}: C = x @ W^T (+bias)(*scale)
// CTA tile 128x128, grid (12, 32): bn>>2 = matrix, bn&3 = N-block.
// 8 warps (4 row x 2 col), warp tile 32x64, K-chunk 32, cp.async dbl-buffer,
// single __syncthreads per chunk. Inputs pre-rounded to tf32.
// ---------------------------------------------------------------------------
#define PBM 128
#define PBK 32
#define PLD 36       // 36 % 32 == 4 -> conflict-free ldmatrix rows
#define TLD 132      // transpose stage leading dim
#define QKV_BUFW ((PBM + 128) * PLD)        // 9216 words per buffer
#define QKV_SMEM (2 * QKV_BUFW * 4)         // 73728 B

__global__ __launch_bounds__(256, 2)
void qkv_mma(const float* __restrict__ A, const float* __restrict__ W4,
             const float* __restrict__ bq, const float* __restrict__ bk,
             const float* __restrict__ bv,
             float* __restrict__ outq, float* __restrict__ outk,
             float* __restrict__ outvt)
{
    extern __shared__ unsigned psm[];

    const int tid  = threadIdx.x;
    const int lane = tid & 31;
    const int wid  = tid >> 5;
    const int wr   = wid >> 1;      // 0..3  (32-row slices)
    const int wc   = wid & 1;       // 0..1  (64-col slices)
    const int g    = lane >> 2;
    const int t4   = lane & 3;
    const int bm   = blockIdx.y;
    const int bnG  = blockIdx.x;    // 0..11
    const int mat  = bnG >> 2;      // 0=Q 1=K 2=V
    const int nb   = bnG & 3;       // N-block within matrix

    const float* Ag = A + (size_t)bm * PBM * DM;
    const float* Wg = W4 + (size_t)mat * DM * DM + (size_t)nb * 128 * DM;
    const float* bias = (mat == 0) ? bq : (mat == 1) ? bk : bv;

    const uint32_t sb   = (uint32_t)__cvta_generic_to_shared(psm);
    const uint32_t BUFB = QKV_BUFW * 4;
    const uint32_t bOff = PBM * PLD * 4;

    const int lr7 = lane & 7, lb3 = (lane >> 3) & 1, lb4 = (lane >> 4) & 1;
    uint32_t aAddr[2], bAddr[4];
#pragma unroll
    for (int i = 0; i < 2; i++)
        aAddr[i] = sb + ((wr*32 + i*16 + lr7 + lb3*8) * PLD + lb4*4) * 4;
#pragma unroll
    for (int jj = 0; jj < 4; jj++)
        bAddr[jj] = sb + bOff + ((wc*64 + jj*16 + lr7 + lb4*8) * PLD + lb3*4) * 4;

    const int cr = tid >> 3, cq = tid & 7;    // copy row (0..31) / quad

    // prologue: chunk 0 -> buf 0
#pragma unroll
    for (int i = 0; i < 4; i++) {
        const int r = cr + i * 32;
        CPA(sb + (r*PLD + cq*4)*4, Ag + (size_t)r * DM + cq*4);
        CPA(sb + bOff + (r*PLD + cq*4)*4, Wg + (size_t)r * DM + cq*4);
    }
    CPC();

    float acc[2][8][4];
#pragma unroll
    for (int i = 0; i < 2; i++)
#pragma unroll
        for (int j = 0; j < 8; j++)
#pragma unroll
            for (int r = 0; r < 4; r++) acc[i][j][r] = 0.f;

    for (int c = 0; c < DM / PBK; c++) {
        const uint32_t cu = (c & 1) * BUFB;
        CPW(0);                 // chunk c arrived (thread-local)
        __syncthreads();        // publish arrivals; proves buf (c+1)&1 consumed
        if (c < DM / PBK - 1) {
            const uint32_t nbuf = ((c + 1) & 1) * BUFB;
            const int k0 = (c + 1) * PBK;
#pragma unroll
            for (int i = 0; i < 4; i++) {
                const int r = cr + i * 32;
                CPA(sb + nbuf + (r*PLD + cq*4)*4, Ag + (size_t)r * DM + k0 + cq*4);
                CPA(sb + nbuf + bOff + (r*PLD + cq*4)*4, Wg + (size_t)r * DM + k0 + cq*4);
            }
            CPC();
        }
#pragma unroll
        for (int kk = 0; kk < PBK / 8; kk++) {
            unsigned af[2][4], bf[4][4];
            ldsm4(af[0], aAddr[0] + cu + kk * 32);
            ldsm4(af[1], aAddr[1] + cu + kk * 32);
#pragma unroll
            for (int jj = 0; jj < 4; jj++)
                ldsm4(bf[jj], bAddr[jj] + cu + kk * 32);
#pragma unroll
            for (int i = 0; i < 2; i++)
#pragma unroll
                for (int j = 0; j < 8; j++)
                    mma8(acc[i][j], af[i], bf[j >> 1] + (j & 1) * 2);
        }
    }

    if (mat == 2) {
        // V: stage (bias-added, tf32-rounded) tile transposed in smem
        float* Ts = (float*)psm;              // 128 cols x TLD
        __syncthreads();
#pragma unroll
        for (int i = 0; i < 2; i++) {
            const int ss = wr*32 + i*16 + g;
#pragma unroll
            for (int j = 0; j < 8; j++) {
                const int cc = wc*64 + j*8 + 2*t4;
                const float b0 = bias[nb*128 + cc], b1 = bias[nb*128 + cc + 1];
                Ts[cc * TLD + ss]           = rtf(acc[i][j][0] + b0);
                Ts[(cc + 1) * TLD + ss]     = rtf(acc[i][j][1] + b1);
                Ts[cc * TLD + ss + 8]       = rtf(acc[i][j][2] + b0);
                Ts[(cc + 1) * TLD + ss + 8] = rtf(acc[i][j][3] + b1);
            }
        }
        __syncthreads();
        const int bb = bm >> 4;
        const int sbase = (bm & 15) * 128;
#pragma unroll
        for (int t = 0; t < 16; t++) {
            const int idx = tid + t * 256;     // 4096 float4 slots
            const int cc = idx >> 5;           // 0..127 col in block
            const int sl = (idx & 31) * 4;     // seq within tile
            const int mc = nb * 128 + cc;
            const int hh = mc >> 6, dd = mc & (DH - 1);
            float4 val = *(float4*)&Ts[cc * TLD + sl];
            *(float4*)(outvt + (((size_t)bb * NH + hh) * DH + dd) * SEQ + sbase + sl) = val;
        }
        return;
    }

    // Q/K: split-heads epilogue, tf32-rounded; Q also scaled by 1/8
    float* out = mat ? outk : outq;
    const float scale = mat ? 1.0f : 0.125f;
#pragma unroll
    for (int i = 0; i < 2; i++) {
        const int row0 = bm * PBM + wr * 32 + i * 16 + g;
        const int row1 = row0 + 8;
        const int b0 = row0 >> 11, s0 = row0 & (SEQ - 1);
        const int b1 = row1 >> 11, s1 = row1 & (SEQ - 1);
#pragma unroll
        for (int j = 0; j < 8; j++) {
            const int col0 = nb * 128 + wc * 64 + j * 8 + 2 * t4;
            const int hh = col0 >> 6, cc = col0 & (DH - 1);
            float* p0 = &out[(((size_t)b0 * NH + hh) * SEQ + s0) * DH + cc];
            p0[0] = rtf((acc[i][j][0] + bias[col0])     * scale);
            p0[1] = rtf((acc[i][j][1] + bias[col0 + 1]) * scale);
            float* p1 = &out[(((size_t)b1 * NH + hh) * SEQ + s1) * DH + cc];
            p1[0] = rtf((acc[i][j][2] + bias[col0])     * scale);
            p1[1] = rtf((acc[i][j][3] + bias[col0 + 1]) * scale);
        }
    }
}

// ---------------------------------------------------------------------------
// O projection: out[4096,512] = att @ Wo^T + bo (fp32 out, flat)
// CTA tile 128x64, grid (8, 32) = 256 CTAs, warp tile 32x32.
// ---------------------------------------------------------------------------
#define O_BUFW ((PBM + 64) * PLD)           // 6912 words
#define O_SMEM (2 * O_BUFW * 4)             // 55296 B

__global__ __launch_bounds__(256, 2)
void o_mma(const float* __restrict__ A, const float* __restrict__ W,
           const float* __restrict__ bias, float* __restrict__ out)
{
    extern __shared__ unsigned psm[];

    const int tid  = threadIdx.x;
    const int lane = tid & 31;
    const int wid  = tid >> 5;
    const int wr   = wid >> 1;
    const int wc   = wid & 1;
    const int g    = lane >> 2;
    const int t4   = lane & 3;
    const int bm   = blockIdx.y;
    const int bn   = blockIdx.x;

    const float* Ag = A + (size_t)bm * PBM * DM;
    const float* Wg = W + (size_t)bn * 64 * DM;

    const uint32_t sb   = (uint32_t)__cvta_generic_to_shared(psm);
    const uint32_t BUFB = O_BUFW * 4;
    const uint32_t bOff = PBM * PLD * 4;

    const int lr7 = lane & 7, lb3 = (lane >> 3) & 1, lb4 = (lane >> 4) & 1;
    uint32_t aAddr[2], bAddr[2];
#pragma unroll
    for (int i = 0; i < 2; i++)
        aAddr[i] = sb + ((wr*32 + i*16 + lr7 + lb3*8) * PLD + lb4*4) * 4;
#pragma unroll
    for (int jj = 0; jj < 2; jj++)
        bAddr[jj] = sb + bOff + ((wc*32 + jj*16 + lr7 + lb4*8) * PLD + lb3*4) * 4;

    const int cr = tid >> 3, cq = tid & 7;

    // prologue: chunk 0 -> buf 0
#pragma unroll
    for (int i = 0; i < 4; i++) {
        const int r = cr + i * 32;
        CPA(sb + (r*PLD + cq*4)*4, Ag + (size_t)r * DM + cq*4);
    }
#pragma unroll
    for (int i = 0; i < 2; i++) {
        const int r = cr + i * 32;
        CPA(sb + bOff + (r*PLD + cq*4)*4, Wg + (size_t)r * DM + cq*4);
    }
    CPC();

    float acc[2][4][4];
#pragma unroll
    for (int i = 0; i < 2; i++)
#pragma unroll
        for (int j = 0; j < 4; j++)
#pragma unroll
            for (int r = 0; r < 4; r++) acc[i][j][r] = 0.f;

    for (int c = 0; c < DM / PBK; c++) {
        const uint32_t cu = (c & 1) * BUFB;
        CPW(0);
        __syncthreads();
        if (c < DM / PBK - 1) {
            const uint32_t nbuf = ((c + 1) & 1) * BUFB;
            const int k0 = (c + 1) * PBK;
#pragma unroll
            for (int i = 0; i < 4; i++) {
                const int r = cr + i * 32;
                CPA(sb + nbuf + (r*PLD + cq*4)*4, Ag + (size_t)r * DM + k0 + cq*4);
            }
#pragma unroll
            for (int i = 0; i < 2; i++) {
                const int r = cr + i * 32;
                CPA(sb + nbuf + bOff + (r*PLD + cq*4)*4, Wg + (size_t)r * DM + k0 + cq*4);
            }
            CPC();
        }
#pragma unroll
        for (int kk = 0; kk < PBK / 8; kk++) {
            unsigned af[2][4], bf[2][4];
            ldsm4(af[0], aAddr[0] + cu + kk * 32);
            ldsm4(af[1], aAddr[1] + cu + kk * 32);
            ldsm4(bf[0], bAddr[0] + cu + kk * 32);
            ldsm4(bf[1], bAddr[1] + cu + kk * 32);
#pragma unroll
            for (int i = 0; i < 2; i++) {
                mma8(acc[i][0], af[i], bf[0]);
                mma8(acc[i][1], af[i], bf[0] + 2);
                mma8(acc[i][2], af[i], bf[1]);
                mma8(acc[i][3], af[i], bf[1] + 2);
            }
        }
    }

#pragma unroll
    for (int i = 0; i < 2; i++) {
        const int row0 = bm * PBM + wr * 32 + i * 16 + g;
        const int row1 = row0 + 8;
#pragma unroll
        for (int j = 0; j < 4; j++) {
            const int col0 = bn * 64 + wc * 32 + j * 8 + 2 * t4;
            float* p0 = &out[(size_t)row0 * DM + col0];
            p0[0] = acc[i][j][0] + bias[col0];
            p0[1] = acc[i][j][1] + bias[col0 + 1];
            float* p1 = &out[(size_t)row1 * DM + col0];
            p1[0] = acc[i][j][2] + bias[col0];
            p1[1] = acc[i][j][3] + bias[col0 + 1];
        }
    }
}

// ---------------------------------------------------------------------------
// Flash attention, tf32 mma + ldmatrix + cp.async double-buffered K/V,
// single __syncthreads per KV tile. Br=128, Bc=64. 8 warps x 16 rows.
// smem: KV bufs 2 x (K 64xALD + V 64xALD) + Ps 128xALD = 104448 B
// ---------------------------------------------------------------------------
#define ALD 68
#define KVSTRIDE (2 * 64 * ALD * 4)                  // bytes per KV buffer
#define ATT_SMEM_BYTES (2 * KVSTRIDE + 128 * ALD * 4) // 104448

__global__ __launch_bounds__(256, 2)
void attn_mma(const float* __restrict__ Q, const float* __restrict__ K,
              const float* __restrict__ VT, float* __restrict__ out)
{
    extern __shared__ unsigned sm[];

    const int tid  = threadIdx.x;
    const int lane = tid & 31;
    const int wid  = tid >> 5;
    const int wrow = wid * 16;
    const int g    = lane >> 2;
    const int t4   = lane & 3;
    const int qt   = blockIdx.x;
    const int h    = blockIdx.y;
    const int b    = blockIdx.z;

    const float* Qg = Q  + (((size_t)b * NH + h) * SEQ + qt * 128) * DH;
    const float* Kg = K  + ((size_t)b * NH + h) * SEQ * DH;
    const float* Vg = VT + ((size_t)b * NH + h) * DH * SEQ;   // [dh][tok]

    const uint32_t sb  = (uint32_t)__cvta_generic_to_shared(sm);
    const uint32_t psB = sb + 2 * KVSTRIDE;   // Ps (and Q staging) base

    const int lr7 = lane & 7, lb3 = (lane >> 3) & 1, lb4 = (lane >> 4) & 1;
    const uint32_t bK0 = sb + ((lr7 + lb4 * 8) * ALD + lb3 * 4) * 4;
    const uint32_t bV0 = bK0 + 64 * ALD * 4;
    const uint32_t aP0 = psB + ((wrow + lr7 + lb3 * 8) * ALD + lb4 * 4) * 4;

    const int r16 = tid >> 4, q16 = tid & 15;

    // ---- prologue: stage Q into Ps region + K0/V0 into buf0, via cp.async
#pragma unroll
    for (int i = 0; i < 8; i++) {
        const int rr = r16 + i * 16;
        CPA(psB + (rr * ALD + q16 * 4) * 4, Qg + rr * DH + q16 * 4);
    }
    CPC();
#pragma unroll
    for (int i = 0; i < 4; i++) {
        const int rr = r16 + i * 16;
        CPA(sb + (rr * ALD + q16 * 4) * 4, Kg + rr * DH + q16 * 4);
        CPA(sb + 64 * ALD * 4 + (rr * ALD + q16 * 4) * 4,
            Vg + (size_t)rr * SEQ + q16 * 4);
    }
    CPC();
    CPW(1);                 // Q group complete
    __syncthreads();

    // Q fragments -> registers (warp-local rows of the staging region)
    unsigned Qf[8][4];
#pragma unroll
    for (int kk = 0; kk < 8; kk++) ldsm4(Qf[kk], aP0 + kk * 32);

    float o[8][4];
#pragma unroll
    for (int j = 0; j < 8; j++)
#pragma unroll
        for (int r = 0; r < 4; r++) o[j][r] = 0.f;
    float mA = -1e30f, mB = -1e30f, lA = 0.f, lB = 0.f;

    for (int kt = 0; kt < SEQ / 64; kt++) {
        const uint32_t cu = (uint32_t)(kt & 1) * KVSTRIDE;
        CPW(0);             // KV stage kt arrived (thread-local)
        __syncthreads();    // publish; proves alternate buffer consumed
        if (kt < SEQ / 64 - 1) {
            const uint32_t nb = (uint32_t)((kt + 1) & 1) * KVSTRIDE;
            const float* Kt = Kg + (size_t)(kt + 1) * 64 * DH;
            const float* Vt = Vg + (kt + 1) * 64;
#pragma unroll
            for (int i = 0; i < 4; i++) {
                const int rr = r16 + i * 16;
                CPA(sb + nb + (rr * ALD + q16 * 4) * 4, Kt + rr * DH + q16 * 4);
                CPA(sb + nb + 64 * ALD * 4 + (rr * ALD + q16 * 4) * 4,
                    Vt + (size_t)rr * SEQ + q16 * 4);
            }
            CPC();
        }

        // ---- S = Q @ K^T (warp: 16 rows x 64 cols)
        float s[8][4];
#pragma unroll
        for (int j = 0; j < 8; j++)
#pragma unroll
            for (int r = 0; r < 4; r++) s[j][r] = 0.f;
#pragma unroll
        for (int kk = 0; kk < 8; kk++) {
#pragma unroll
            for (int jj = 0; jj < 4; jj++) {
                unsigned bk[4];
                ldsm4(bk, bK0 + cu + jj * (16 * ALD * 4) + kk * 32);
                mma8(s[2 * jj],     Qf[kk], bk);
                mma8(s[2 * jj + 1], Qf[kk], bk + 2);
            }
        }

        // ---- in-register online softmax (rows g / g+8, quad shfl)
        float mxA = -1e30f, mxB = -1e30f;
#pragma unroll
        for (int j = 0; j < 8; j++) {
            mxA = fmaxf(mxA, fmaxf(s[j][0], s[j][1]));
            mxB = fmaxf(mxB, fmaxf(s[j][2], s[j][3]));
        }
        mxA = fmaxf(mxA, __shfl_xor_sync(0xffffffffu, mxA, 1));
        mxA = fmaxf(mxA, __shfl_xor_sync(0xffffffffu, mxA, 2));
        mxB = fmaxf(mxB, __shfl_xor_sync(0xffffffffu, mxB, 1));
        mxB = fmaxf(mxB, __shfl_xor_sync(0xffffffffu, mxB, 2));
        const float mnA = fmaxf(mA, mxA), mnB = fmaxf(mB, mxB);
        const float alA = __expf(mA - mnA), alB = __expf(mB - mnB);
        float suA = 0.f, suB = 0.f;
#pragma unroll
        for (int j = 0; j < 8; j++) {
            s[j][0] = __expf(s[j][0] - mnA);
            s[j][1] = __expf(s[j][1] - mnA);
            s[j][2] = __expf(s[j][2] - mnB);
            s[j][3] = __expf(s[j][3] - mnB);
            suA += s[j][0] + s[j][1];
            suB += s[j][2] + s[j][3];
        }
        suA += __shfl_xor_sync(0xffffffffu, suA, 1);
        suA += __shfl_xor_sync(0xffffffffu, suA, 2);
        suB += __shfl_xor_sync(0xffffffffu, suB, 1);
        suB += __shfl_xor_sync(0xffffffffu, suB, 2);
        lA = lA * alA + suA;  mA = mnA;
        lB = lB * alB + suB;  mB = mnB;

        // rescale O
#pragma unroll
        for (int j = 0; j < 8; j++) {
            o[j][0] *= alA; o[j][1] *= alA;
            o[j][2] *= alB; o[j][3] *= alB;
        }

        // ---- write P (RNA-rounded tf32 bits), read back as A-frags
        unsigned* Ps = sm + 2 * (KVSTRIDE / 4);
        __syncwarp();
#pragma unroll
        for (int j = 0; j < 8; j++) {
            uint2 u0, u1;
            u0.x = f2tf(s[j][0]); u0.y = f2tf(s[j][1]);
            u1.x = f2tf(s[j][2]); u1.y = f2tf(s[j][3]);
            *(uint2*)&Ps[(wrow + g)     * ALD + j * 8 + 2 * t4] = u0;
            *(uint2*)&Ps[(wrow + g + 8) * ALD + j * 8 + 2 * t4] = u1;
        }
        __syncwarp();

        // ---- O += P @ V
#pragma unroll
        for (int kc = 0; kc < 8; kc++) {
            unsigned ap[4];
            ldsm4(ap, aP0 + kc * 32);
#pragma unroll
            for (int jj = 0; jj < 4; jj++) {
                unsigned bv[4];
                ldsm4(bv, bV0 + cu + jj * (16 * ALD * 4) + kc * 32);
                mma8(o[2 * jj],     ap, bv);
                mma8(o[2 * jj + 1], ap, bv + 2);
            }
        }
    }

    // ---- epilogue (tf32-rounded so the O-projection's loads are exact)
    const float invA = 1.f / lA, invB = 1.f / lB;
    const int rA = qt * 128 + wrow + g;
    float* oA = out + ((size_t)(b * SEQ + rA)) * DM + h * DH;
    float* oB = oA + (size_t)8 * DM;
#pragma unroll
    for (int j = 0; j < 8; j++) {
        const int col = j * 8 + 2 * t4;
        float2 vA, vB;
        vA.x = rtf(o[j][0] * invA); vA.y = rtf(o[j][1] * invA);
        vB.x = rtf(o[j][2] * invB); vB.y = rtf(o[j][3] * invB);
        *(float2*)(oA + col) = vA;
        *(float2*)(oB + col) = vB;
    }
}

// ---------------------------------------------------------------------------
extern "C" void kernel_launch(void* const* d_in, const int* in_sizes, int n_in,
                              void* d_out, int out_size)
{
    const float* x  = (const float*)d_in[0];
    const float* Wq = (const float*)d_in[1];
    const float* bq = (const float*)d_in[2];
    const float* Wk = (const float*)d_in[3];
    const float* bk = (const float*)d_in[4];
    const float* Wv = (const float*)d_in[5];
    const float* bv = (const float*)d_in[6];
    const float* Wo = (const float*)d_in[7];
    const float* bo = (const float*)d_in[8];
    float* out = (float*)d_out;

    float *xr, *wr_, *q, *k, *vt, *att;
    cudaGetSymbolAddress((void**)&xr,  g_x);
    cudaGetSymbolAddress((void**)&wr_, g_w);
    cudaGetSymbolAddress((void**)&q,   g_q);
    cudaGetSymbolAddress((void**)&k,   g_k);
    cudaGetSymbolAddress((void**)&vt,  g_vt);
    cudaGetSymbolAddress((void**)&att, g_att);

    cudaFuncSetAttribute(qkv_mma,
        cudaFuncAttributeMaxDynamicSharedMemorySize, QKV_SMEM);
    cudaFuncSetAttribute(o_mma,
        cudaFuncAttributeMaxDynamicSharedMemorySize, O_SMEM);
    cudaFuncSetAttribute(attn_mma,
        cudaFuncAttributeMaxDynamicSharedMemorySize, ATT_SMEM_BYTES);

    const int XN4 = NTOK * DM / 4;      // 524288
    const int WN4 = DM * DM / 4;        // 65536

    // launches 0..4; attn is launch index 5 (ncu -s 5 captures it)
    prep_x<<<XN4 / 256, 256>>>(x,  xr,              XN4);
    prep_x<<<WN4 / 256, 256>>>(Wq, wr_ + 0*DM*DM,   WN4);
    prep_x<<<WN4 / 256, 256>>>(Wk, wr_ + 1*DM*DM,   WN4);
    prep_x<<<WN4 / 256, 256>>>(Wv, wr_ + 2*DM*DM,   WN4);

    qkv_mma<<<dim3(12, NTOK / PBM), 256, QKV_SMEM>>>(xr, wr_, bq, bk, bv, q, k, vt);

    attn_mma<<<dim3(SEQ / 128, NH, BAT), 256, ATT_SMEM_BYTES>>>(q, k, vt, att);

    // Wo prep deferred until after attn (not on the critical path earlier)
    prep_x<<<WN4 / 256, 256>>>(Wo, wr_ + 3*DM*DM, WN4);
    o_mma<<<dim3(8, NTOK / PBM), 256, O_SMEM>>>(att, wr_ + 3*DM*DM, bo, out);
}